// round 12
// baseline (speedup 1.0000x reference)
#include <cuda_runtime.h>
#include <cuda_bf16.h>
#include <math.h>
#include <stdint.h>

// ---------------- problem constants ----------------
#define BB    8
#define HH    56
#define WW    56
#define DIM   256
#define FFND  1024
#define NHD   8
#define KDIM  32
#define SPAT  (HH*WW)          // 3136
#define NPIX  (BB*SPAT)        // 25088
#define SCALEF 0.17677669529663687f   // 32^-0.5

// ---------------- scratch (device globals; no allocs allowed) ----------------
__device__ float g_x1  [NPIX*DIM];
__device__ float g_xn  [NPIX*DIM];
__device__ float g_q   [NPIX*DIM];
__device__ float g_k   [NPIX*DIM];
__device__ float g_v   [NPIX*DIM];
__device__ float g_lep [NPIX*DIM];
__device__ float g_vw  [NPIX*DIM];
__device__ float g_ao  [NPIX*DIM];   // attn + lepe (fp32)
__device__ float g_x2  [NPIX*DIM];
__device__ float g_hdn [NPIX*FFND];
__device__ float g_hdn2[NPIX*FFND];
__device__ float g_sin [SPAT*KDIM];
__device__ float g_cos [SPAT*KDIM];

// bf16 hi/lo split buffers
__device__ __nv_bfloat16 g_xnh[NPIX*DIM],  g_xnl[NPIX*DIM];
__device__ __nv_bfloat16 g_aoh[NPIX*DIM],  g_aol[NPIX*DIM];
__device__ __nv_bfloat16 g_h2h[NPIX*FFND], g_h2l[NPIX*FFND];
__device__ __nv_bfloat16 g_wqh[DIM*DIM],  g_wql[DIM*DIM];
__device__ __nv_bfloat16 g_wkh[DIM*DIM],  g_wkl[DIM*DIM];
__device__ __nv_bfloat16 g_wvh[DIM*DIM],  g_wvl[DIM*DIM];
__device__ __nv_bfloat16 g_woh[DIM*DIM],  g_wol[DIM*DIM];
__device__ __nv_bfloat16 g_f1h[FFND*DIM], g_f1l[FFND*DIM];
__device__ __nv_bfloat16 g_f2h[DIM*FFND], g_f2l[DIM*FFND];

// ---------------- helpers ----------------
__device__ __forceinline__ uint32_t smem_u32(const void* p) {
    uint32_t a;
    asm("{ .reg .u64 t; cvta.to.shared.u64 t, %1; cvt.u32.u64 %0, t; }" : "=r"(a) : "l"(p));
    return a;
}
__device__ __forceinline__ void cpasync16(uint32_t dst, const void* src) {
    asm volatile("cp.async.cg.shared.global [%0], [%1], 16;" :: "r"(dst), "l"(src));
}
#define CP_COMMIT() asm volatile("cp.async.commit_group;" ::: "memory")
#define CP_WAIT(n)  asm volatile("cp.async.wait_group %0;" :: "n"(n) : "memory")
#define BAR(id)     asm volatile("bar.sync %0, 128;" :: "r"(id) : "memory")

__device__ __forceinline__ void ldsm4(uint32_t* r, uint32_t addr) {
    asm volatile("ldmatrix.sync.aligned.m8n8.x4.shared.b16 {%0,%1,%2,%3}, [%4];"
                 : "=r"(r[0]), "=r"(r[1]), "=r"(r[2]), "=r"(r[3]) : "r"(addr));
}
__device__ __forceinline__ void mma16816(float* c, const uint32_t* a, const uint32_t* b) {
    asm volatile("mma.sync.aligned.m16n8k16.row.col.f32.bf16.bf16.f32 "
        "{%0,%1,%2,%3}, {%4,%5,%6,%7}, {%8,%9}, {%0,%1,%2,%3};"
        : "+f"(c[0]), "+f"(c[1]), "+f"(c[2]), "+f"(c[3])
        : "r"(a[0]), "r"(a[1]), "r"(a[2]), "r"(a[3]), "r"(b[0]), "r"(b[1]));
}

// ---------------- RoPE table (fp64 for accuracy, tiny) ----------------
__global__ void rope_table_kernel() {
    int i = blockIdx.x * 256 + threadIdx.x;
    if (i >= SPAT * 16) return;
    int pos = i >> 4, t = i & 15;
    double ang = pow(10000.0, -(double)t / 15.0);
    double ph  = (double)pos * ang;
    float s = (float)sin(ph), c = (float)cos(ph);
    int b = pos * KDIM + 2 * t;
    g_sin[b] = s; g_sin[b + 1] = s;
    g_cos[b] = c; g_cos[b + 1] = c;
}

// ---------------- split-convert helpers ----------------
__device__ __forceinline__ void split_bf16(float y, __nv_bfloat16& h, __nv_bfloat16& l) {
    h = __float2bfloat16(y);
    l = __float2bfloat16(y - __bfloat162float(h));
}
__device__ __forceinline__ uint32_t pack_bf16x2(__nv_bfloat16 a, __nv_bfloat16 b) {
    __nv_bfloat162 v(a, b);
    return *(uint32_t*)&v;
}

// vectorized weight convert: 4 elems/thread
__global__ __launch_bounds__(256) void wcvt4_kernel(const float* __restrict__ w,
                                                    __nv_bfloat16* __restrict__ h,
                                                    __nv_bfloat16* __restrict__ l, int n4) {
    int i = blockIdx.x * 256 + threadIdx.x;
    if (i >= n4) return;
    float4 v = ((const float4*)w)[i];
    __nv_bfloat16 h0, h1, h2, h3, l0, l1, l2, l3;
    split_bf16(v.x, h0, l0); split_bf16(v.y, h1, l1);
    split_bf16(v.z, h2, l2); split_bf16(v.w, h3, l3);
    uint2 hv, lv;
    hv.x = pack_bf16x2(h0, h1); hv.y = pack_bf16x2(h2, h3);
    lv.x = pack_bf16x2(l0, l1); lv.y = pack_bf16x2(l2, l3);
    ((uint2*)h)[i] = hv;
    ((uint2*)l)[i] = lv;
}

// ---------------- depthwise 3x3 (cpe), 4 channels/thread ----------------
__global__ __launch_bounds__(256) void cpe_kernel(const float* __restrict__ x,
                                                  const float* __restrict__ kw,
                                                  const float* __restrict__ kb,
                                                  float* __restrict__ out) {
    int idx = blockIdx.x * 256 + threadIdx.x;        // NPIX*64 threads
    int c = (idx & 63) * 4; int pix = idx >> 6;
    int w = pix % WW; int hb = pix / WW; int h = hb % HH; int b = hb / HH;
    float4 acc = *(const float4*)(kb + c);
    #pragma unroll
    for (int kh = 0; kh < 3; kh++) {
        int hh = h + kh - 1; if ((unsigned)hh >= HH) continue;
        #pragma unroll
        for (int kv = 0; kv < 3; kv++) {
            int ww = w + kv - 1; if ((unsigned)ww >= WW) continue;
            float4 xv = *(const float4*)(x + ((size_t)b * SPAT + hh * WW + ww) * DIM + c);
            float4 kv4 = *(const float4*)(kw + (kh * 3 + kv) * DIM + c);
            acc.x = fmaf(xv.x, kv4.x, acc.x); acc.y = fmaf(xv.y, kv4.y, acc.y);
            acc.z = fmaf(xv.z, kv4.z, acc.z); acc.w = fmaf(xv.w, kv4.w, acc.w);
        }
    }
    float4 xc = *(const float4*)(x + (size_t)pix * DIM + c);
    acc.x += xc.x; acc.y += xc.y; acc.z += xc.z; acc.w += xc.w;
    *(float4*)(out + (size_t)pix * DIM + c) = acc;
}

// ---------------- LayerNorm -> float + hi/lo ----------------
__global__ __launch_bounds__(256) void ln3_kernel(const float* __restrict__ x,
                                                  const float* __restrict__ gam,
                                                  const float* __restrict__ bet,
                                                  float* __restrict__ of,
                                                  __nv_bfloat16* __restrict__ oh,
                                                  __nv_bfloat16* __restrict__ ol) {
    int warp = threadIdx.x >> 5, lane = threadIdx.x & 31;
    int pix = blockIdx.x * 8 + warp;
    const float* row = x + (size_t)pix * DIM;
    float v[8], s = 0.f, s2 = 0.f;
    #pragma unroll
    for (int u = 0; u < 8; u++) { v[u] = row[lane + u * 32]; s += v[u]; s2 += v[u] * v[u]; }
    #pragma unroll
    for (int o = 16; o; o >>= 1) {
        s  += __shfl_xor_sync(0xffffffffu, s,  o);
        s2 += __shfl_xor_sync(0xffffffffu, s2, o);
    }
    float mean = s * (1.f / DIM);
    float var  = s2 * (1.f / DIM) - mean * mean;
    float rstd = rsqrtf(var + 1e-6f);
    #pragma unroll
    for (int u = 0; u < 8; u++) {
        int c = lane + u * 32;
        float y = (v[u] - mean) * rstd * gam[c] + bet[c];
        of[(size_t)pix * DIM + c] = y;
        __nv_bfloat16 h, l; split_bf16(y, h, l);
        oh[(size_t)pix * DIM + c] = h;
        ol[(size_t)pix * DIM + c] = l;
    }
}

// ---------------- hybrid GEMM: HMMA warps 0-3 (rows 0-63), FFMA warps 4-7 (rows 64-127)
#define EPI_QROPE 0
#define EPI_KROPE 1
#define EPI_VSCAT 2
#define EPI_RES   3
#define EPI_GELU  4

// smem map
#define FF_A      0                       // Asf[16][68] float
#define FF_B      4352                    // Bsf[16][68] float
#define HM_BASE   8704
#define HM_AH     0
#define HM_AL     5120                    // 64*40*2
#define HM_BH     10240
#define HM_BL     15360
#define HM_STAGE  20480
#define HG_SMEM   (8704 + 2*20480)        // 49664

__device__ __forceinline__ float geluf(float x) {
    return 0.5f * x * (1.0f + erff(x * 0.70710678118654752f));
}

template<int EPI>
__global__ __launch_bounds__(256, 2) void hgemm(const float* __restrict__ Af,
                                                const __nv_bfloat16* __restrict__ Ah,
                                                const __nv_bfloat16* __restrict__ Al,
                                                const float* __restrict__ Wf,
                                                const __nv_bfloat16* __restrict__ Wh,
                                                const __nv_bfloat16* __restrict__ Wl,
                                                const float* __restrict__ bias,
                                                const float* __restrict__ res,
                                                float* __restrict__ Cout,
                                                int K, int M) {
    extern __shared__ __align__(16) char smem[];
    const int tid = threadIdx.x, wid = tid >> 5, l = tid & 31;
    const int row0 = blockIdx.x * 128, col0 = blockIdx.y * 64;

    if (wid < 4) {
        // ================= HMMA half: rows row0..row0+63 =================
        const uint32_t sb = smem_u32(smem) + HM_BASE;
        const int wm = wid & 1, wn = wid >> 1;

        float acc[2][4][4];
        #pragma unroll
        for (int mt = 0; mt < 2; mt++)
            #pragma unroll
            for (int nt = 0; nt < 4; nt++)
                #pragma unroll
                for (int e = 0; e < 4; e++) acc[mt][nt][e] = 0.f;

        int a_off[2], b_off[2];
        #pragma unroll
        for (int mt = 0; mt < 2; mt++) {
            int r = wm * 32 + mt * 16 + (l & 7) + ((l >> 3) & 1) * 8;
            a_off[mt] = r * 40 + (l >> 4) * 8;
        }
        #pragma unroll
        for (int nt2 = 0; nt2 < 2; nt2++) {
            int r = wn * 32 + nt2 * 16 + (l & 7) + (l >> 4) * 8;
            b_off[nt2] = r * 40 + ((l >> 3) & 1) * 8;
        }

        const int nstage = K >> 5;
        auto load_stage = [&](int st, int buf) {
            const int k0 = st << 5;
            const uint32_t base = sb + buf * HM_STAGE;
            #pragma unroll
            for (int i = 0; i < 2; i++) {
                int c = tid + i * 128;
                int r = c >> 2, kc = c & 3;
                size_t ga = (size_t)(row0 + r) * K + k0 + kc * 8;
                size_t gb = (size_t)(col0 + r) * K + k0 + kc * 8;
                cpasync16(base + HM_AH + r * 80 + kc * 16, Ah + ga);
                cpasync16(base + HM_AL + r * 80 + kc * 16, Al + ga);
                cpasync16(base + HM_BH + r * 80 + kc * 16, Wh + gb);
                cpasync16(base + HM_BL + r * 80 + kc * 16, Wl + gb);
            }
        };

        load_stage(0, 0);
        CP_COMMIT();
        for (int st = 0; st < nstage; st++) {
            const int buf = st & 1;
            if (st + 1 < nstage) {
                load_stage(st + 1, (st + 1) & 1);
                CP_COMMIT();
                CP_WAIT(1);
            } else {
                CP_WAIT(0);
            }
            BAR(2);
            const uint32_t base = sb + buf * HM_STAGE;
            #pragma unroll
            for (int ks = 0; ks < 2; ks++) {
                uint32_t ah[2][4], al[2][4], bh4[2][4], bl4[2][4];
                #pragma unroll
                for (int mt = 0; mt < 2; mt++) {
                    ldsm4(ah[mt], base + HM_AH + (a_off[mt] + ks * 16) * 2);
                    ldsm4(al[mt], base + HM_AL + (a_off[mt] + ks * 16) * 2);
                }
                #pragma unroll
                for (int nt2 = 0; nt2 < 2; nt2++) {
                    ldsm4(bh4[nt2], base + HM_BH + (b_off[nt2] + ks * 16) * 2);
                    ldsm4(bl4[nt2], base + HM_BL + (b_off[nt2] + ks * 16) * 2);
                }
                #pragma unroll
                for (int mt = 0; mt < 2; mt++)
                    #pragma unroll
                    for (int nt = 0; nt < 4; nt++) {
                        const uint32_t* bh = &bh4[nt >> 1][(nt & 1) * 2];
                        const uint32_t* bl = &bl4[nt >> 1][(nt & 1) * 2];
                        mma16816(acc[mt][nt], ah[mt], bh);
                        mma16816(acc[mt][nt], ah[mt], bl);
                        mma16816(acc[mt][nt], al[mt], bh);
                    }
            }
            BAR(2);
        }

        // ---- HMMA epilogue ----
        #pragma unroll
        for (int mt = 0; mt < 2; mt++) {
            #pragma unroll
            for (int half = 0; half < 2; half++) {
                const int r = row0 + wm * 32 + mt * 16 + (l >> 2) + half * 8;
                if (EPI == EPI_RES) {
                    #pragma unroll
                    for (int nt = 0; nt < 4; nt++) {
                        const int c = col0 + wn * 32 + nt * 8 + (l & 3) * 2;
                        float v0 = acc[mt][nt][half * 2 + 0] + bias[c];
                        float v1 = acc[mt][nt][half * 2 + 1] + bias[c + 1];
                        float2 rv = *(const float2*)(res + (size_t)r * M + c);
                        float2 o; o.x = v0 + rv.x; o.y = v1 + rv.y;
                        *(float2*)(Cout + (size_t)r * M + c) = o;
                    }
                } else if (EPI == EPI_GELU) {
                    #pragma unroll
                    for (int nt = 0; nt < 4; nt++) {
                        const int c = col0 + wn * 32 + nt * 8 + (l & 3) * 2;
                        float2 o;
                        o.x = geluf(acc[mt][nt][half * 2 + 0] + bias[c]);
                        o.y = geluf(acc[mt][nt][half * 2 + 1] + bias[c + 1]);
                        *(float2*)(Cout + (size_t)r * M + c) = o;
                    }
                } else {
                    const int b = r / SPAT, sp = r - b * SPAT;
                    #pragma unroll
                    for (int nt = 0; nt < 4; nt++) {
                        const int c = col0 + wn * 32 + nt * 8 + (l & 3) * 2;
                        float v0 = acc[mt][nt][half * 2 + 0] + bias[c];
                        float v1 = acc[mt][nt][half * 2 + 1] + bias[c + 1];
                        const int n = c >> 5, d = c & 31;
                        float* dst = Cout + (size_t)(b * NHD + n) * (SPAT * KDIM) + sp * KDIM + d;
                        if (EPI == EPI_VSCAT) {
                            dst[0] = v0; dst[1] = v1;
                        } else {
                            if (EPI == EPI_KROPE) { v0 *= SCALEF; v1 *= SCALEF; }
                            float s = g_sin[sp * KDIM + d], co = g_cos[sp * KDIM + d];
                            dst[0] = v0 * co - v1 * s;
                            dst[1] = v1 * co + v0 * s;
                        }
                    }
                }
            }
        }
    } else {
        // ================= FFMA half: rows row0+64..row0+127 =================
        float (*Asf)[68] = (float (*)[68])(smem + FF_A);
        float (*Bsf)[68] = (float (*)[68])(smem + FF_B);
        const int t2 = tid - 128;
        const int tx = t2 & 15, ty = t2 >> 4;

        float acc[8][4];
        #pragma unroll
        for (int i = 0; i < 8; i++)
            #pragma unroll
            for (int j = 0; j < 4; j++) acc[i][j] = 0.f;

        const int lr = t2 >> 1, lk = (t2 & 1) * 8;
        const size_t aoff = (size_t)(row0 + 64 + lr) * K + lk;
        const size_t boff = (size_t)(col0 + lr) * K + lk;

        float4 a0 = *(const float4*)(Af + aoff);
        float4 a1 = *(const float4*)(Af + aoff + 4);
        float4 b0 = *(const float4*)(Wf + boff);
        float4 b1 = *(const float4*)(Wf + boff + 4);

        for (int k0 = 0; k0 < K; k0 += 16) {
            Asf[lk + 0][lr] = a0.x; Asf[lk + 1][lr] = a0.y;
            Asf[lk + 2][lr] = a0.z; Asf[lk + 3][lr] = a0.w;
            Asf[lk + 4][lr] = a1.x; Asf[lk + 5][lr] = a1.y;
            Asf[lk + 6][lr] = a1.z; Asf[lk + 7][lr] = a1.w;
            Bsf[lk + 0][lr] = b0.x; Bsf[lk + 1][lr] = b0.y;
            Bsf[lk + 2][lr] = b0.z; Bsf[lk + 3][lr] = b0.w;
            Bsf[lk + 4][lr] = b1.x; Bsf[lk + 5][lr] = b1.y;
            Bsf[lk + 6][lr] = b1.z; Bsf[lk + 7][lr] = b1.w;
            BAR(1);

            const int kn = k0 + 16;
            if (kn < K) {
                a0 = *(const float4*)(Af + aoff + kn);
                a1 = *(const float4*)(Af + aoff + kn + 4);
                b0 = *(const float4*)(Wf + boff + kn);
                b1 = *(const float4*)(Wf + boff + kn + 4);
            }

            #pragma unroll
            for (int kk = 0; kk < 16; kk++) {
                float4 av0 = *(const float4*)&Asf[kk][ty * 8];
                float4 av1 = *(const float4*)&Asf[kk][ty * 8 + 4];
                float4 bv  = *(const float4*)&Bsf[kk][tx * 4];
                float ar[8] = {av0.x, av0.y, av0.z, av0.w, av1.x, av1.y, av1.z, av1.w};
                float br[4] = {bv.x, bv.y, bv.z, bv.w};
                #pragma unroll
                for (int i = 0; i < 8; i++)
                    #pragma unroll
                    for (int j = 0; j < 4; j++)
                        acc[i][j] = fmaf(ar[i], br[j], acc[i][j]);
            }
            BAR(1);
        }

        // ---- FFMA epilogue ----
        #pragma unroll
        for (int i = 0; i < 8; i++) {
            const int r = row0 + 64 + ty * 8 + i;
            if (EPI == EPI_RES) {
                const int c = col0 + tx * 4;
                const float4 rv = *(const float4*)(res + (size_t)r * M + c);
                float4 o;
                o.x = acc[i][0] + bias[c + 0] + rv.x;
                o.y = acc[i][1] + bias[c + 1] + rv.y;
                o.z = acc[i][2] + bias[c + 2] + rv.z;
                o.w = acc[i][3] + bias[c + 3] + rv.w;
                *(float4*)(Cout + (size_t)r * M + c) = o;
            } else if (EPI == EPI_GELU) {
                const int c = col0 + tx * 4;
                float4 o;
                o.x = geluf(acc[i][0] + bias[c + 0]);
                o.y = geluf(acc[i][1] + bias[c + 1]);
                o.z = geluf(acc[i][2] + bias[c + 2]);
                o.w = geluf(acc[i][3] + bias[c + 3]);
                *(float4*)(Cout + (size_t)r * M + c) = o;
            } else {
                const int b = r / SPAT, sp = r - b * SPAT;
                #pragma unroll
                for (int jp = 0; jp < 4; jp += 2) {
                    const int c = col0 + tx * 4 + jp;
                    float v0 = acc[i][jp]     + bias[c];
                    float v1 = acc[i][jp + 1] + bias[c + 1];
                    const int n = c >> 5, d = c & 31;
                    float* dst = Cout + (size_t)(b * NHD + n) * (SPAT * KDIM) + sp * KDIM + d;
                    if (EPI == EPI_VSCAT) {
                        dst[0] = v0; dst[1] = v1;
                    } else {
                        if (EPI == EPI_KROPE) { v0 *= SCALEF; v1 *= SCALEF; }
                        float s = g_sin[sp * KDIM + d], co = g_cos[sp * KDIM + d];
                        dst[0] = v0 * co - v1 * s;
                        dst[1] = v1 * co + v0 * s;
                    }
                }
            }
        }
    }
}

// ---------------- lepe: 5x5 depthwise conv of v, 4 channels/thread ----------------
__global__ __launch_bounds__(256) void lepe_kernel(const float* __restrict__ v,
                                                   const float* __restrict__ kw,
                                                   const float* __restrict__ kb,
                                                   float* __restrict__ out) {
    int idx = blockIdx.x * 256 + threadIdx.x;        // NPIX*64
    int c = (idx & 63) * 4; int pix = idx >> 6;
    int w = pix % WW; int hb = pix / WW; int h = hb % HH; int b = hb / HH;
    int n = c >> 5, d = c & 31;                       // c..c+3 same head (d<=28)
    const float* vb = v + (size_t)(b * NHD + n) * (SPAT * KDIM) + d;
    float4 acc = *(const float4*)(kb + c);
    #pragma unroll
    for (int kh = 0; kh < 5; kh++) {
        int hh = h + kh - 2; if ((unsigned)hh >= HH) continue;
        #pragma unroll
        for (int kv = 0; kv < 5; kv++) {
            int ww = w + kv - 2; if ((unsigned)ww >= WW) continue;
            float4 vv = *(const float4*)(vb + (hh * WW + ww) * KDIM);
            float4 kv4 = *(const float4*)(kw + (kh * 5 + kv) * DIM + c);
            acc.x = fmaf(vv.x, kv4.x, acc.x); acc.y = fmaf(vv.y, kv4.y, acc.y);
            acc.z = fmaf(vv.z, kv4.z, acc.z); acc.w = fmaf(vv.w, kv4.w, acc.w);
        }
    }
    *(float4*)(out + (size_t)pix * DIM + c) = acc;
}

// ---------------- row attention ----------------
__global__ __launch_bounds__(64) void rowattn_kernel(const float* __restrict__ q,
                                                     const float* __restrict__ k,
                                                     const float* __restrict__ v,
                                                     float* __restrict__ vw) {
    int blk = blockIdx.x;
    int bn = blk / HH, h = blk % HH;
    const size_t base = ((size_t)bn * SPAT + h * WW) * KDIM;
    __shared__ float Ks[WW * KDIM], Vs[WW * KDIM], Ss[WW][57];
    int t = threadIdx.x;
    for (int i = t; i < WW * KDIM / 4; i += 64) {
        ((float4*)Ks)[i] = ((const float4*)(k + base))[i];
        ((float4*)Vs)[i] = ((const float4*)(v + base))[i];
    }
    __syncthreads();
    if (t < WW) {
        float qr[KDIM];
        #pragma unroll
        for (int d = 0; d < KDIM; d++) qr[d] = q[base + t * KDIM + d];
        float mx = -1e30f;
        for (int j = 0; j < WW; j++) {
            float s = 0.f;
            #pragma unroll
            for (int d = 0; d < KDIM; d++) s = fmaf(qr[d], Ks[j * KDIM + d], s);
            Ss[t][j] = s; mx = fmaxf(mx, s);
        }
        float sum = 0.f;
        for (int j = 0; j < WW; j++) { float e = __expf(Ss[t][j] - mx); Ss[t][j] = e; sum += e; }
        float inv = 1.f / sum;
        float acc[KDIM];
        #pragma unroll
        for (int d = 0; d < KDIM; d++) acc[d] = 0.f;
        for (int j = 0; j < WW; j++) {
            float p = Ss[t][j];
            #pragma unroll
            for (int d = 0; d < KDIM; d++) acc[d] = fmaf(p, Vs[j * KDIM + d], acc[d]);
        }
        #pragma unroll
        for (int d = 0; d < KDIM; d++) vw[base + t * KDIM + d] = acc[d] * inv;
    }
}

// ---------------- column attention + (lepe add + split) fused epilogue -----------
__global__ __launch_bounds__(64) void colattn_kernel(const float* __restrict__ q,
                                                     const float* __restrict__ k,
                                                     const float* __restrict__ vw,
                                                     const float* __restrict__ lep,
                                                     float* __restrict__ aof,
                                                     __nv_bfloat16* __restrict__ aoh,
                                                     __nv_bfloat16* __restrict__ aol) {
    int blk = blockIdx.x;
    int bn = blk / WW, w = blk % WW;
    const size_t base = (size_t)bn * (SPAT * KDIM) + w * KDIM;
    __shared__ float Ks[HH * KDIM], Vs[HH * KDIM], Ss[HH][57];
    int t = threadIdx.x;
    for (int i = t; i < HH * KDIM / 4; i += 64) {
        int j = i >> 3, d4 = (i & 7) * 4;
        float4 kv = *(const float4*)(k  + base + (size_t)j * (WW * KDIM) + d4);
        float4 vv = *(const float4*)(vw + base + (size_t)j * (WW * KDIM) + d4);
        *(float4*)(Ks + j * KDIM + d4) = kv;
        *(float4*)(Vs + j * KDIM + d4) = vv;
    }
    __syncthreads();
    if (t < HH) {
        float qr[KDIM];
        #pragma unroll
        for (int d = 0; d < KDIM; d++) qr[d] = q[base + (size_t)t * (WW * KDIM) + d];
        float mx = -1e30f;
        for (int j = 0; j < HH; j++) {
            float s = 0.f;
            #pragma unroll
            for (int d = 0; d < KDIM; d++) s = fmaf(qr[d], Ks[j * KDIM + d], s);
            Ss[t][j] = s; mx = fmaxf(mx, s);
        }
        float sum = 0.f;
        for (int j = 0; j < HH; j++) { float e = __expf(Ss[t][j] - mx); Ss[t][j] = e; sum += e; }
        float inv = 1.f / sum;
        float acc[KDIM];
        #pragma unroll
        for (int d = 0; d < KDIM; d++) acc[d] = 0.f;
        for (int j = 0; j < HH; j++) {
            float p = Ss[t][j];
            #pragma unroll
            for (int d = 0; d < KDIM; d++) acc[d] = fmaf(p, Vs[j * KDIM + d], acc[d]);
        }
        const size_t o = base + (size_t)t * (WW * KDIM);
        #pragma unroll
        for (int d = 0; d < KDIM; d += 4) {
            float4 lv = *(const float4*)(lep + o + d);
            float4 y;
            y.x = acc[d + 0] * inv + lv.x;
            y.y = acc[d + 1] * inv + lv.y;
            y.z = acc[d + 2] * inv + lv.z;
            y.w = acc[d + 3] * inv + lv.w;
            *(float4*)(aof + o + d) = y;
            __nv_bfloat16 h0, h1, h2, h3, l0, l1, l2, l3;
            split_bf16(y.x, h0, l0); split_bf16(y.y, h1, l1);
            split_bf16(y.z, h2, l2); split_bf16(y.w, h3, l3);
            uint2 hv, lv2;
            hv.x = pack_bf16x2(h0, h1); hv.y = pack_bf16x2(h2, h3);
            lv2.x = pack_bf16x2(l0, l1); lv2.y = pack_bf16x2(l2, l3);
            *(uint2*)(aoh + o + d) = hv;
            *(uint2*)(aol + o + d) = lv2;
        }
    }
}

// ---------------- FFN depthwise 3x3 -> float + hi/lo, 4 channels/thread ----------
__global__ __launch_bounds__(256) void dwffn3_kernel(const float* __restrict__ x,
                                                     const float* __restrict__ kw,
                                                     const float* __restrict__ kb,
                                                     float* __restrict__ of,
                                                     __nv_bfloat16* __restrict__ oh,
                                                     __nv_bfloat16* __restrict__ ol) {
    int idx = blockIdx.x * 256 + threadIdx.x;        // NPIX*256
    int c = (idx & 255) * 4; int pix = idx >> 8;
    int w = pix % WW; int hb = pix / WW; int h = hb % HH; int b = hb / HH;
    float4 acc = *(const float4*)(kb + c);
    #pragma unroll
    for (int kh = 0; kh < 3; kh++) {
        int hh = h + kh - 1; if ((unsigned)hh >= HH) continue;
        #pragma unroll
        for (int kv = 0; kv < 3; kv++) {
            int ww = w + kv - 1; if ((unsigned)ww >= WW) continue;
            float4 xv = *(const float4*)(x + ((size_t)b * SPAT + hh * WW + ww) * FFND + c);
            float4 kv4 = *(const float4*)(kw + (kh * 3 + kv) * FFND + c);
            acc.x = fmaf(xv.x, kv4.x, acc.x); acc.y = fmaf(xv.y, kv4.y, acc.y);
            acc.z = fmaf(xv.z, kv4.z, acc.z); acc.w = fmaf(xv.w, kv4.w, acc.w);
        }
    }
    float4 xc = *(const float4*)(x + (size_t)pix * FFND + c);
    float4 y;
    y.x = acc.x + xc.x; y.y = acc.y + xc.y; y.z = acc.z + xc.z; y.w = acc.w + xc.w;
    *(float4*)(of + (size_t)pix * FFND + c) = y;
    __nv_bfloat16 h0, h1, h2, h3, l0, l1, l2, l3;
    split_bf16(y.x, h0, l0); split_bf16(y.y, h1, l1);
    split_bf16(y.z, h2, l2); split_bf16(y.w, h3, l3);
    uint2 hv, lv;
    hv.x = pack_bf16x2(h0, h1); hv.y = pack_bf16x2(h2, h3);
    lv.x = pack_bf16x2(l0, l1); lv.y = pack_bf16x2(l2, l3);
    *(uint2*)(oh + (size_t)pix * FFND + c) = hv;
    *(uint2*)(ol + (size_t)pix * FFND + c) = lv;
}

// ---------------- launch ----------------
extern "C" void kernel_launch(void* const* d_in, const int* in_sizes, int n_in,
                              void* d_out, int out_size) {
    (void)in_sizes; (void)n_in; (void)out_size;
    const float* x      = (const float*)d_in[0];
    const float* cpe_w  = (const float*)d_in[1];
    const float* cpe_b  = (const float*)d_in[2];
    const float* ln1_g  = (const float*)d_in[3];
    const float* ln1_b  = (const float*)d_in[4];
    const float* wq     = (const float*)d_in[5];
    const float* bq     = (const float*)d_in[6];
    const float* wk     = (const float*)d_in[7];
    const float* bk     = (const float*)d_in[8];
    const float* wv     = (const float*)d_in[9];
    const float* bv     = (const float*)d_in[10];
    const float* lepe_w = (const float*)d_in[11];
    const float* lepe_b = (const float*)d_in[12];
    const float* wo     = (const float*)d_in[13];
    const float* bo     = (const float*)d_in[14];
    const float* ln2_g  = (const float*)d_in[15];
    const float* ln2_b  = (const float*)d_in[16];
    const float* fc1_w  = (const float*)d_in[17];
    const float* fc1_b  = (const float*)d_in[18];
    const float* dw_w   = (const float*)d_in[19];
    const float* dw_b   = (const float*)d_in[20];
    const float* fc2_w  = (const float*)d_in[21];
    const float* fc2_b  = (const float*)d_in[22];
    float* outp = (float*)d_out;

    float *x1, *xn, *q, *k, *v, *lep, *vw, *ao, *x2, *hdn, *hdn2;
    cudaGetSymbolAddress((void**)&x1,   g_x1);
    cudaGetSymbolAddress((void**)&xn,   g_xn);
    cudaGetSymbolAddress((void**)&q,    g_q);
    cudaGetSymbolAddress((void**)&k,    g_k);
    cudaGetSymbolAddress((void**)&v,    g_v);
    cudaGetSymbolAddress((void**)&lep,  g_lep);
    cudaGetSymbolAddress((void**)&vw,   g_vw);
    cudaGetSymbolAddress((void**)&ao,   g_ao);
    cudaGetSymbolAddress((void**)&x2,   g_x2);
    cudaGetSymbolAddress((void**)&hdn,  g_hdn);
    cudaGetSymbolAddress((void**)&hdn2, g_hdn2);

    __nv_bfloat16 *xnh, *xnl, *aoh, *aol, *h2h, *h2l;
    __nv_bfloat16 *wqh, *wql, *wkh, *wkl, *wvh, *wvl, *woh, *wol, *f1h, *f1l, *f2h, *f2l;
    cudaGetSymbolAddress((void**)&xnh, g_xnh); cudaGetSymbolAddress((void**)&xnl, g_xnl);
    cudaGetSymbolAddress((void**)&aoh, g_aoh); cudaGetSymbolAddress((void**)&aol, g_aol);
    cudaGetSymbolAddress((void**)&h2h, g_h2h); cudaGetSymbolAddress((void**)&h2l, g_h2l);
    cudaGetSymbolAddress((void**)&wqh, g_wqh); cudaGetSymbolAddress((void**)&wql, g_wql);
    cudaGetSymbolAddress((void**)&wkh, g_wkh); cudaGetSymbolAddress((void**)&wkl, g_wkl);
    cudaGetSymbolAddress((void**)&wvh, g_wvh); cudaGetSymbolAddress((void**)&wvl, g_wvl);
    cudaGetSymbolAddress((void**)&woh, g_woh); cudaGetSymbolAddress((void**)&wol, g_wol);
    cudaGetSymbolAddress((void**)&f1h, g_f1h); cudaGetSymbolAddress((void**)&f1l, g_f1l);
    cudaGetSymbolAddress((void**)&f2h, g_f2h); cudaGetSymbolAddress((void**)&f2l, g_f2l);

    cudaFuncSetAttribute(hgemm<EPI_QROPE>, cudaFuncAttributeMaxDynamicSharedMemorySize, HG_SMEM);
    cudaFuncSetAttribute(hgemm<EPI_KROPE>, cudaFuncAttributeMaxDynamicSharedMemorySize, HG_SMEM);
    cudaFuncSetAttribute(hgemm<EPI_VSCAT>, cudaFuncAttributeMaxDynamicSharedMemorySize, HG_SMEM);
    cudaFuncSetAttribute(hgemm<EPI_RES>,   cudaFuncAttributeMaxDynamicSharedMemorySize, HG_SMEM);
    cudaFuncSetAttribute(hgemm<EPI_GELU>,  cudaFuncAttributeMaxDynamicSharedMemorySize, HG_SMEM);

    rope_table_kernel<<<(SPAT * 16 + 255) / 256, 256>>>();
    cpe_kernel<<<NPIX * 64 / 256, 256>>>(x, cpe_w, cpe_b, x1);
    ln3_kernel<<<NPIX / 8, 256>>>(x1, ln1_g, ln1_b, xn, xnh, xnl);
    wcvt4_kernel<<<DIM * DIM / 1024, 256>>>(wq, wqh, wql, DIM * DIM / 4);
    wcvt4_kernel<<<DIM * DIM / 1024, 256>>>(wk, wkh, wkl, DIM * DIM / 4);
    wcvt4_kernel<<<DIM * DIM / 1024, 256>>>(wv, wvh, wvl, DIM * DIM / 4);

    dim3 gD(NPIX / 128, DIM / 64);       // 196 x 4
    hgemm<EPI_QROPE><<<gD, 256, HG_SMEM>>>(xn, xnh, xnl, wq, wqh, wql, bq, nullptr, q, DIM, DIM);
    hgemm<EPI_KROPE><<<gD, 256, HG_SMEM>>>(xn, xnh, xnl, wk, wkh, wkl, bk, nullptr, k, DIM, DIM);
    hgemm<EPI_VSCAT><<<gD, 256, HG_SMEM>>>(xn, xnh, xnl, wv, wvh, wvl, bv, nullptr, v, DIM, DIM);

    lepe_kernel<<<NPIX * 64 / 256, 256>>>(v, lepe_w, lepe_b, lep);
    rowattn_kernel<<<BB * NHD * HH, 64>>>(q, k, v, vw);
    colattn_kernel<<<BB * NHD * WW, 64>>>(q, k, vw, lep, ao, aoh, aol);

    wcvt4_kernel<<<DIM * DIM / 1024, 256>>>(wo, woh, wol, DIM * DIM / 4);
    hgemm<EPI_RES><<<gD, 256, HG_SMEM>>>(ao, aoh, aol, wo, woh, wol, bo, x1, x2, DIM, DIM);

    ln3_kernel<<<NPIX / 8, 256>>>(x2, ln2_g, ln2_b, xn, xnh, xnl);

    dim3 gF(NPIX / 128, FFND / 64);      // 196 x 16
    wcvt4_kernel<<<FFND * DIM / 1024, 256>>>(fc1_w, f1h, f1l, FFND * DIM / 4);
    hgemm<EPI_GELU><<<gF, 256, HG_SMEM>>>(xn, xnh, xnl, fc1_w, f1h, f1l, fc1_b, nullptr, hdn, DIM, FFND);
    dwffn3_kernel<<<NPIX * 256 / 256, 256>>>(hdn, dw_w, dw_b, hdn2, h2h, h2l);
    wcvt4_kernel<<<DIM * FFND / 1024, 256>>>(fc2_w, f2h, f2l, DIM * FFND / 4);
    hgemm<EPI_RES><<<gD, 256, HG_SMEM>>>(hdn2, h2h, h2l, fc2_w, f2h, f2l, fc2_b, x2, outp, FFND, DIM);
}

// round 13
// speedup vs baseline: 1.2554x; 1.2554x over previous
#include <cuda_runtime.h>
#include <cuda_bf16.h>
#include <math.h>
#include <stdint.h>

// ---------------- problem constants ----------------
#define BB    8
#define HH    56
#define WW    56
#define DIM   256
#define FFND  1024
#define NHD   8
#define KDIM  32
#define SPAT  (HH*WW)          // 3136
#define NPIX  (BB*SPAT)        // 25088
#define SCALEF 0.17677669529663687f   // 32^-0.5

// ---------------- scratch (device globals; no allocs allowed) ----------------
__device__ float g_x1  [NPIX*DIM];
__device__ float g_xn  [NPIX*DIM];
__device__ float g_q   [NPIX*DIM];
__device__ float g_k   [NPIX*DIM];
__device__ float g_v   [NPIX*DIM];
__device__ float g_lep [NPIX*DIM];
__device__ float g_vw  [NPIX*DIM];
__device__ float g_ao  [NPIX*DIM];   // attn + lepe (fp32)
__device__ float g_x2  [NPIX*DIM];
__device__ float g_hdn [NPIX*FFND];
__device__ float g_hdn2[NPIX*FFND];
__device__ float g_sin [SPAT*KDIM];
__device__ float g_cos [SPAT*KDIM];

// bf16 hi/lo split buffers
__device__ __nv_bfloat16 g_xnh[NPIX*DIM],  g_xnl[NPIX*DIM];
__device__ __nv_bfloat16 g_aoh[NPIX*DIM],  g_aol[NPIX*DIM];
__device__ __nv_bfloat16 g_h2h[NPIX*FFND], g_h2l[NPIX*FFND];
__device__ __nv_bfloat16 g_wqh[DIM*DIM],  g_wql[DIM*DIM];
__device__ __nv_bfloat16 g_wkh[DIM*DIM],  g_wkl[DIM*DIM];
__device__ __nv_bfloat16 g_wvh[DIM*DIM],  g_wvl[DIM*DIM];
__device__ __nv_bfloat16 g_woh[DIM*DIM],  g_wol[DIM*DIM];
__device__ __nv_bfloat16 g_f1h[FFND*DIM], g_f1l[FFND*DIM];
__device__ __nv_bfloat16 g_f2h[DIM*FFND], g_f2l[DIM*FFND];

// ---------------- helpers ----------------
__device__ __forceinline__ uint32_t smem_u32(const void* p) {
    uint32_t a;
    asm("{ .reg .u64 t; cvta.to.shared.u64 t, %1; cvt.u32.u64 %0, t; }" : "=r"(a) : "l"(p));
    return a;
}
__device__ __forceinline__ void cpasync16(uint32_t dst, const void* src) {
    asm volatile("cp.async.cg.shared.global [%0], [%1], 16;" :: "r"(dst), "l"(src));
}
#define CP_COMMIT() asm volatile("cp.async.commit_group;" ::: "memory")
#define CP_WAIT(n)  asm volatile("cp.async.wait_group %0;" :: "n"(n) : "memory")
#define BAR(id)     asm volatile("bar.sync %0, 128;" :: "r"(id) : "memory")

__device__ __forceinline__ void ldsm4(uint32_t* r, uint32_t addr) {
    asm volatile("ldmatrix.sync.aligned.m8n8.x4.shared.b16 {%0,%1,%2,%3}, [%4];"
                 : "=r"(r[0]), "=r"(r[1]), "=r"(r[2]), "=r"(r[3]) : "r"(addr));
}
__device__ __forceinline__ void mma16816(float* c, const uint32_t* a, const uint32_t* b) {
    asm volatile("mma.sync.aligned.m16n8k16.row.col.f32.bf16.bf16.f32 "
        "{%0,%1,%2,%3}, {%4,%5,%6,%7}, {%8,%9}, {%0,%1,%2,%3};"
        : "+f"(c[0]), "+f"(c[1]), "+f"(c[2]), "+f"(c[3])
        : "r"(a[0]), "r"(a[1]), "r"(a[2]), "r"(a[3]), "r"(b[0]), "r"(b[1]));
}

// ---------------- RoPE table (fp64 for accuracy, tiny) ----------------
__global__ void rope_table_kernel() {
    int i = blockIdx.x * 256 + threadIdx.x;
    if (i >= SPAT * 16) return;
    int pos = i >> 4, t = i & 15;
    double ang = pow(10000.0, -(double)t / 15.0);
    double ph  = (double)pos * ang;
    float s = (float)sin(ph), c = (float)cos(ph);
    int b = pos * KDIM + 2 * t;
    g_sin[b] = s; g_sin[b + 1] = s;
    g_cos[b] = c; g_cos[b + 1] = c;
}

// ---------------- split-convert helpers ----------------
__device__ __forceinline__ void split_bf16(float y, __nv_bfloat16& h, __nv_bfloat16& l) {
    h = __float2bfloat16(y);
    l = __float2bfloat16(y - __bfloat162float(h));
}

__global__ __launch_bounds__(256) void wcvt_kernel(const float* __restrict__ w,
                                                   __nv_bfloat16* __restrict__ h,
                                                   __nv_bfloat16* __restrict__ l, int n) {
    int i = blockIdx.x * 256 + threadIdx.x;
    if (i >= n) return;
    split_bf16(w[i], h[i], l[i]);
}

// ---------------- depthwise 3x3 (cpe): out = x + conv(x) + bias ----------------
__global__ __launch_bounds__(256) void cpe_kernel(const float* __restrict__ x,
                                                  const float* __restrict__ kw,
                                                  const float* __restrict__ kb,
                                                  float* __restrict__ out) {
    int idx = blockIdx.x * 256 + threadIdx.x;
    int c = idx & (DIM - 1); int pix = idx >> 8;
    int w = pix % WW; int hb = pix / WW; int h = hb % HH; int b = hb / HH;
    float acc = kb[c];
    #pragma unroll
    for (int kh = 0; kh < 3; kh++) {
        int hh = h + kh - 1; if ((unsigned)hh >= HH) continue;
        #pragma unroll
        for (int kv = 0; kv < 3; kv++) {
            int ww = w + kv - 1; if ((unsigned)ww >= WW) continue;
            acc = fmaf(x[((size_t)b * SPAT + hh * WW + ww) * DIM + c],
                       kw[(kh * 3 + kv) * DIM + c], acc);
        }
    }
    out[idx] = x[idx] + acc;
}

// ---------------- LayerNorm -> float + hi/lo ----------------
__global__ __launch_bounds__(256) void ln3_kernel(const float* __restrict__ x,
                                                  const float* __restrict__ gam,
                                                  const float* __restrict__ bet,
                                                  float* __restrict__ of,
                                                  __nv_bfloat16* __restrict__ oh,
                                                  __nv_bfloat16* __restrict__ ol) {
    int warp = threadIdx.x >> 5, lane = threadIdx.x & 31;
    int pix = blockIdx.x * 8 + warp;
    const float* row = x + (size_t)pix * DIM;
    float v[8], s = 0.f, s2 = 0.f;
    #pragma unroll
    for (int u = 0; u < 8; u++) { v[u] = row[lane + u * 32]; s += v[u]; s2 += v[u] * v[u]; }
    #pragma unroll
    for (int o = 16; o; o >>= 1) {
        s  += __shfl_xor_sync(0xffffffffu, s,  o);
        s2 += __shfl_xor_sync(0xffffffffu, s2, o);
    }
    float mean = s * (1.f / DIM);
    float var  = s2 * (1.f / DIM) - mean * mean;
    float rstd = rsqrtf(var + 1e-6f);
    #pragma unroll
    for (int u = 0; u < 8; u++) {
        int c = lane + u * 32;
        float y = (v[u] - mean) * rstd * gam[c] + bet[c];
        of[(size_t)pix * DIM + c] = y;
        __nv_bfloat16 h, l; split_bf16(y, h, l);
        oh[(size_t)pix * DIM + c] = h;
        ol[(size_t)pix * DIM + c] = l;
    }
}

// ---------------- hybrid GEMM: HMMA warps 0-3 (rows 0-63), FFMA warps 4-7 (rows 64-127)
#define EPI_QROPE 0
#define EPI_KROPE 1
#define EPI_VSCAT 2
#define EPI_RES   3
#define EPI_GELU  4

// smem map
#define FF_A      0                       // Asf[16][68] float
#define FF_B      4352                    // Bsf[16][68] float
#define HM_BASE   8704
#define HM_AH     0
#define HM_AL     5120                    // 64*40*2
#define HM_BH     10240
#define HM_BL     15360
#define HM_STAGE  20480
#define HG_SMEM   (8704 + 2*20480)        // 49664

__device__ __forceinline__ float geluf(float x) {
    return 0.5f * x * (1.0f + erff(x * 0.70710678118654752f));
}

template<int EPI>
__global__ __launch_bounds__(256, 2) void hgemm(const float* __restrict__ Af,
                                                const __nv_bfloat16* __restrict__ Ah,
                                                const __nv_bfloat16* __restrict__ Al,
                                                const float* __restrict__ Wf,
                                                const __nv_bfloat16* __restrict__ Wh,
                                                const __nv_bfloat16* __restrict__ Wl,
                                                const float* __restrict__ bias,
                                                const float* __restrict__ res,
                                                float* __restrict__ Cout,
                                                int K, int M) {
    extern __shared__ __align__(16) char smem[];
    const int tid = threadIdx.x, wid = tid >> 5, l = tid & 31;
    const int row0 = blockIdx.x * 128, col0 = blockIdx.y * 64;

    if (wid < 4) {
        // ================= HMMA half: rows row0..row0+63 =================
        const uint32_t sb = smem_u32(smem) + HM_BASE;
        const int wm = wid & 1, wn = wid >> 1;

        float acc[2][4][4];
        #pragma unroll
        for (int mt = 0; mt < 2; mt++)
            #pragma unroll
            for (int nt = 0; nt < 4; nt++)
                #pragma unroll
                for (int e = 0; e < 4; e++) acc[mt][nt][e] = 0.f;

        int a_off[2], b_off[2];
        #pragma unroll
        for (int mt = 0; mt < 2; mt++) {
            int r = wm * 32 + mt * 16 + (l & 7) + ((l >> 3) & 1) * 8;
            a_off[mt] = r * 40 + (l >> 4) * 8;
        }
        #pragma unroll
        for (int nt2 = 0; nt2 < 2; nt2++) {
            int r = wn * 32 + nt2 * 16 + (l & 7) + (l >> 4) * 8;
            b_off[nt2] = r * 40 + ((l >> 3) & 1) * 8;
        }

        const int nstage = K >> 5;
        auto load_stage = [&](int st, int buf) {
            const int k0 = st << 5;
            const uint32_t base = sb + buf * HM_STAGE;
            #pragma unroll
            for (int i = 0; i < 2; i++) {
                int c = tid + i * 128;
                int r = c >> 2, kc = c & 3;
                size_t ga = (size_t)(row0 + r) * K + k0 + kc * 8;
                size_t gb = (size_t)(col0 + r) * K + k0 + kc * 8;
                cpasync16(base + HM_AH + r * 80 + kc * 16, Ah + ga);
                cpasync16(base + HM_AL + r * 80 + kc * 16, Al + ga);
                cpasync16(base + HM_BH + r * 80 + kc * 16, Wh + gb);
                cpasync16(base + HM_BL + r * 80 + kc * 16, Wl + gb);
            }
        };

        load_stage(0, 0);
        CP_COMMIT();
        for (int st = 0; st < nstage; st++) {
            const int buf = st & 1;
            if (st + 1 < nstage) {
                load_stage(st + 1, (st + 1) & 1);
                CP_COMMIT();
                CP_WAIT(1);
            } else {
                CP_WAIT(0);
            }
            BAR(2);
            const uint32_t base = sb + buf * HM_STAGE;
            #pragma unroll
            for (int ks = 0; ks < 2; ks++) {
                uint32_t ah[2][4], al[2][4], bh4[2][4], bl4[2][4];
                #pragma unroll
                for (int mt = 0; mt < 2; mt++) {
                    ldsm4(ah[mt], base + HM_AH + (a_off[mt] + ks * 16) * 2);
                    ldsm4(al[mt], base + HM_AL + (a_off[mt] + ks * 16) * 2);
                }
                #pragma unroll
                for (int nt2 = 0; nt2 < 2; nt2++) {
                    ldsm4(bh4[nt2], base + HM_BH + (b_off[nt2] + ks * 16) * 2);
                    ldsm4(bl4[nt2], base + HM_BL + (b_off[nt2] + ks * 16) * 2);
                }
                #pragma unroll
                for (int mt = 0; mt < 2; mt++)
                    #pragma unroll
                    for (int nt = 0; nt < 4; nt++) {
                        const uint32_t* bh = &bh4[nt >> 1][(nt & 1) * 2];
                        const uint32_t* bl = &bl4[nt >> 1][(nt & 1) * 2];
                        mma16816(acc[mt][nt], ah[mt], bh);
                        mma16816(acc[mt][nt], ah[mt], bl);
                        mma16816(acc[mt][nt], al[mt], bh);
                    }
            }
            BAR(2);
        }

        // ---- HMMA epilogue ----
        #pragma unroll
        for (int mt = 0; mt < 2; mt++) {
            #pragma unroll
            for (int half = 0; half < 2; half++) {
                const int r = row0 + wm * 32 + mt * 16 + (l >> 2) + half * 8;
                if (EPI == EPI_RES) {
                    #pragma unroll
                    for (int nt = 0; nt < 4; nt++) {
                        const int c = col0 + wn * 32 + nt * 8 + (l & 3) * 2;
                        float v0 = acc[mt][nt][half * 2 + 0] + bias[c];
                        float v1 = acc[mt][nt][half * 2 + 1] + bias[c + 1];
                        float2 rv = *(const float2*)(res + (size_t)r * M + c);
                        float2 o; o.x = v0 + rv.x; o.y = v1 + rv.y;
                        *(float2*)(Cout + (size_t)r * M + c) = o;
                    }
                } else if (EPI == EPI_GELU) {
                    #pragma unroll
                    for (int nt = 0; nt < 4; nt++) {
                        const int c = col0 + wn * 32 + nt * 8 + (l & 3) * 2;
                        float2 o;
                        o.x = geluf(acc[mt][nt][half * 2 + 0] + bias[c]);
                        o.y = geluf(acc[mt][nt][half * 2 + 1] + bias[c + 1]);
                        *(float2*)(Cout + (size_t)r * M + c) = o;
                    }
                } else {
                    const int b = r / SPAT, sp = r - b * SPAT;
                    #pragma unroll
                    for (int nt = 0; nt < 4; nt++) {
                        const int c = col0 + wn * 32 + nt * 8 + (l & 3) * 2;
                        float v0 = acc[mt][nt][half * 2 + 0] + bias[c];
                        float v1 = acc[mt][nt][half * 2 + 1] + bias[c + 1];
                        const int n = c >> 5, d = c & 31;
                        float* dst = Cout + (size_t)(b * NHD + n) * (SPAT * KDIM) + sp * KDIM + d;
                        if (EPI == EPI_VSCAT) {
                            dst[0] = v0; dst[1] = v1;
                        } else {
                            if (EPI == EPI_KROPE) { v0 *= SCALEF; v1 *= SCALEF; }
                            float s = g_sin[sp * KDIM + d], co = g_cos[sp * KDIM + d];
                            dst[0] = v0 * co - v1 * s;
                            dst[1] = v1 * co + v0 * s;
                        }
                    }
                }
            }
        }
    } else {
        // ================= FFMA half: rows row0+64..row0+127 =================
        float (*Asf)[68] = (float (*)[68])(smem + FF_A);
        float (*Bsf)[68] = (float (*)[68])(smem + FF_B);
        const int t2 = tid - 128;
        const int tx = t2 & 15, ty = t2 >> 4;

        float acc[8][4];
        #pragma unroll
        for (int i = 0; i < 8; i++)
            #pragma unroll
            for (int j = 0; j < 4; j++) acc[i][j] = 0.f;

        const int lr = t2 >> 1, lk = (t2 & 1) * 8;
        const size_t aoff = (size_t)(row0 + 64 + lr) * K + lk;
        const size_t boff = (size_t)(col0 + lr) * K + lk;

        float4 a0 = *(const float4*)(Af + aoff);
        float4 a1 = *(const float4*)(Af + aoff + 4);
        float4 b0 = *(const float4*)(Wf + boff);
        float4 b1 = *(const float4*)(Wf + boff + 4);

        for (int k0 = 0; k0 < K; k0 += 16) {
            Asf[lk + 0][lr] = a0.x; Asf[lk + 1][lr] = a0.y;
            Asf[lk + 2][lr] = a0.z; Asf[lk + 3][lr] = a0.w;
            Asf[lk + 4][lr] = a1.x; Asf[lk + 5][lr] = a1.y;
            Asf[lk + 6][lr] = a1.z; Asf[lk + 7][lr] = a1.w;
            Bsf[lk + 0][lr] = b0.x; Bsf[lk + 1][lr] = b0.y;
            Bsf[lk + 2][lr] = b0.z; Bsf[lk + 3][lr] = b0.w;
            Bsf[lk + 4][lr] = b1.x; Bsf[lk + 5][lr] = b1.y;
            Bsf[lk + 6][lr] = b1.z; Bsf[lk + 7][lr] = b1.w;
            BAR(1);

            const int kn = k0 + 16;
            if (kn < K) {
                a0 = *(const float4*)(Af + aoff + kn);
                a1 = *(const float4*)(Af + aoff + kn + 4);
                b0 = *(const float4*)(Wf + boff + kn);
                b1 = *(const float4*)(Wf + boff + kn + 4);
            }

            #pragma unroll
            for (int kk = 0; kk < 16; kk++) {
                float4 av0 = *(const float4*)&Asf[kk][ty * 8];
                float4 av1 = *(const float4*)&Asf[kk][ty * 8 + 4];
                float4 bv  = *(const float4*)&Bsf[kk][tx * 4];
                float ar[8] = {av0.x, av0.y, av0.z, av0.w, av1.x, av1.y, av1.z, av1.w};
                float br[4] = {bv.x, bv.y, bv.z, bv.w};
                #pragma unroll
                for (int i = 0; i < 8; i++)
                    #pragma unroll
                    for (int j = 0; j < 4; j++)
                        acc[i][j] = fmaf(ar[i], br[j], acc[i][j]);
            }
            BAR(1);
        }

        // ---- FFMA epilogue ----
        #pragma unroll
        for (int i = 0; i < 8; i++) {
            const int r = row0 + 64 + ty * 8 + i;
            if (EPI == EPI_RES) {
                const int c = col0 + tx * 4;
                const float4 rv = *(const float4*)(res + (size_t)r * M + c);
                float4 o;
                o.x = acc[i][0] + bias[c + 0] + rv.x;
                o.y = acc[i][1] + bias[c + 1] + rv.y;
                o.z = acc[i][2] + bias[c + 2] + rv.z;
                o.w = acc[i][3] + bias[c + 3] + rv.w;
                *(float4*)(Cout + (size_t)r * M + c) = o;
            } else if (EPI == EPI_GELU) {
                const int c = col0 + tx * 4;
                float4 o;
                o.x = geluf(acc[i][0] + bias[c + 0]);
                o.y = geluf(acc[i][1] + bias[c + 1]);
                o.z = geluf(acc[i][2] + bias[c + 2]);
                o.w = geluf(acc[i][3] + bias[c + 3]);
                *(float4*)(Cout + (size_t)r * M + c) = o;
            } else {
                const int b = r / SPAT, sp = r - b * SPAT;
                #pragma unroll
                for (int jp = 0; jp < 4; jp += 2) {
                    const int c = col0 + tx * 4 + jp;
                    float v0 = acc[i][jp]     + bias[c];
                    float v1 = acc[i][jp + 1] + bias[c + 1];
                    const int n = c >> 5, d = c & 31;
                    float* dst = Cout + (size_t)(b * NHD + n) * (SPAT * KDIM) + sp * KDIM + d;
                    if (EPI == EPI_VSCAT) {
                        dst[0] = v0; dst[1] = v1;
                    } else {
                        if (EPI == EPI_KROPE) { v0 *= SCALEF; v1 *= SCALEF; }
                        float s = g_sin[sp * KDIM + d], co = g_cos[sp * KDIM + d];
                        dst[0] = v0 * co - v1 * s;
                        dst[1] = v1 * co + v0 * s;
                    }
                }
            }
        }
    }
}

// ---------------- lepe: 5x5 depthwise conv of v ----------------
__global__ __launch_bounds__(256) void lepe_kernel(const float* __restrict__ v,
                                                   const float* __restrict__ kw,
                                                   const float* __restrict__ kb,
                                                   float* __restrict__ out) {
    int idx = blockIdx.x * 256 + threadIdx.x;
    int c = idx & (DIM - 1); int pix = idx >> 8;
    int w = pix % WW; int hb = pix / WW; int h = hb % HH; int b = hb / HH;
    int n = c >> 5, d = c & 31;
    const float* vb = v + (size_t)(b * NHD + n) * (SPAT * KDIM) + d;
    float acc = kb[c];
    #pragma unroll
    for (int kh = 0; kh < 5; kh++) {
        int hh = h + kh - 2; if ((unsigned)hh >= HH) continue;
        #pragma unroll
        for (int kv = 0; kv < 5; kv++) {
            int ww = w + kv - 2; if ((unsigned)ww >= WW) continue;
            acc = fmaf(vb[(hh * WW + ww) * KDIM], kw[(kh * 5 + kv) * DIM + c], acc);
        }
    }
    out[idx] = acc;
}

// ---------------- row attention ----------------
__global__ __launch_bounds__(64) void rowattn_kernel(const float* __restrict__ q,
                                                     const float* __restrict__ k,
                                                     const float* __restrict__ v,
                                                     float* __restrict__ vw) {
    int blk = blockIdx.x;
    int bn = blk / HH, h = blk % HH;
    const size_t base = ((size_t)bn * SPAT + h * WW) * KDIM;
    __shared__ float Ks[WW * KDIM], Vs[WW * KDIM], Ss[WW][57];
    int t = threadIdx.x;
    for (int i = t; i < WW * KDIM; i += 64) { Ks[i] = k[base + i]; Vs[i] = v[base + i]; }
    __syncthreads();
    if (t < WW) {
        float qr[KDIM];
        #pragma unroll
        for (int d = 0; d < KDIM; d++) qr[d] = q[base + t * KDIM + d];
        float mx = -1e30f;
        for (int j = 0; j < WW; j++) {
            float s = 0.f;
            #pragma unroll
            for (int d = 0; d < KDIM; d++) s = fmaf(qr[d], Ks[j * KDIM + d], s);
            Ss[t][j] = s; mx = fmaxf(mx, s);
        }
        float sum = 0.f;
        for (int j = 0; j < WW; j++) { float e = __expf(Ss[t][j] - mx); Ss[t][j] = e; sum += e; }
        float inv = 1.f / sum;
        float acc[KDIM];
        #pragma unroll
        for (int d = 0; d < KDIM; d++) acc[d] = 0.f;
        for (int j = 0; j < WW; j++) {
            float p = Ss[t][j];
            #pragma unroll
            for (int d = 0; d < KDIM; d++) acc[d] = fmaf(p, Vs[j * KDIM + d], acc[d]);
        }
        #pragma unroll
        for (int d = 0; d < KDIM; d++) vw[base + t * KDIM + d] = acc[d] * inv;
    }
}

// ---------------- column attention + fused (lepe add + hi/lo split) ----------------
__global__ __launch_bounds__(64) void colattn_kernel(const float* __restrict__ q,
                                                     const float* __restrict__ k,
                                                     const float* __restrict__ vw,
                                                     const float* __restrict__ lep,
                                                     float* __restrict__ aof,
                                                     __nv_bfloat16* __restrict__ aoh,
                                                     __nv_bfloat16* __restrict__ aol) {
    int blk = blockIdx.x;
    int bn = blk / WW, w = blk % WW;
    const size_t base = (size_t)bn * (SPAT * KDIM) + w * KDIM;
    __shared__ float Ks[HH * KDIM], Vs[HH * KDIM], Ss[HH][57];
    int t = threadIdx.x;
    for (int i = t; i < HH * KDIM; i += 64) {
        int j = i >> 5, d = i & 31;
        Ks[i] = k[base + (size_t)j * (WW * KDIM) + d];
        Vs[i] = vw[base + (size_t)j * (WW * KDIM) + d];
    }
    __syncthreads();
    if (t < HH) {
        float qr[KDIM];
        #pragma unroll
        for (int d = 0; d < KDIM; d++) qr[d] = q[base + (size_t)t * (WW * KDIM) + d];
        float mx = -1e30f;
        for (int j = 0; j < HH; j++) {
            float s = 0.f;
            #pragma unroll
            for (int d = 0; d < KDIM; d++) s = fmaf(qr[d], Ks[j * KDIM + d], s);
            Ss[t][j] = s; mx = fmaxf(mx, s);
        }
        float sum = 0.f;
        for (int j = 0; j < HH; j++) { float e = __expf(Ss[t][j] - mx); Ss[t][j] = e; sum += e; }
        float inv = 1.f / sum;
        float acc[KDIM];
        #pragma unroll
        for (int d = 0; d < KDIM; d++) acc[d] = 0.f;
        for (int j = 0; j < HH; j++) {
            float p = Ss[t][j];
            #pragma unroll
            for (int d = 0; d < KDIM; d++) acc[d] = fmaf(p, Vs[j * KDIM + d], acc[d]);
        }
        const size_t o = base + (size_t)t * (WW * KDIM);
        #pragma unroll
        for (int d = 0; d < KDIM; d++) {
            float y = acc[d] * inv + lep[o + d];
            aof[o + d] = y;
            __nv_bfloat16 h, l; split_bf16(y, h, l);
            aoh[o + d] = h;
            aol[o + d] = l;
        }
    }
}

// ---------------- FFN depthwise 3x3 -> float + hi/lo ----------------
__global__ __launch_bounds__(256) void dwffn3_kernel(const float* __restrict__ x,
                                                     const float* __restrict__ kw,
                                                     const float* __restrict__ kb,
                                                     float* __restrict__ of,
                                                     __nv_bfloat16* __restrict__ oh,
                                                     __nv_bfloat16* __restrict__ ol) {
    int idx = blockIdx.x * 256 + threadIdx.x;
    int c = idx & (FFND - 1); int pix = idx >> 10;
    int w = pix % WW; int hb = pix / WW; int h = hb % HH; int b = hb / HH;
    float acc = kb[c];
    #pragma unroll
    for (int kh = 0; kh < 3; kh++) {
        int hh = h + kh - 1; if ((unsigned)hh >= HH) continue;
        #pragma unroll
        for (int kv = 0; kv < 3; kv++) {
            int ww = w + kv - 1; if ((unsigned)ww >= WW) continue;
            acc = fmaf(x[((size_t)b * SPAT + hh * WW + ww) * FFND + c],
                       kw[(kh * 3 + kv) * FFND + c], acc);
        }
    }
    float y = x[idx] + acc;
    of[idx] = y;
    __nv_bfloat16 hi, lo; split_bf16(y, hi, lo);
    oh[idx] = hi; ol[idx] = lo;
}

// ---------------- launch ----------------
extern "C" void kernel_launch(void* const* d_in, const int* in_sizes, int n_in,
                              void* d_out, int out_size) {
    (void)in_sizes; (void)n_in; (void)out_size;
    const float* x      = (const float*)d_in[0];
    const float* cpe_w  = (const float*)d_in[1];
    const float* cpe_b  = (const float*)d_in[2];
    const float* ln1_g  = (const float*)d_in[3];
    const float* ln1_b  = (const float*)d_in[4];
    const float* wq     = (const float*)d_in[5];
    const float* bq     = (const float*)d_in[6];
    const float* wk     = (const float*)d_in[7];
    const float* bk     = (const float*)d_in[8];
    const float* wv     = (const float*)d_in[9];
    const float* bv     = (const float*)d_in[10];
    const float* lepe_w = (const float*)d_in[11];
    const float* lepe_b = (const float*)d_in[12];
    const float* wo     = (const float*)d_in[13];
    const float* bo     = (const float*)d_in[14];
    const float* ln2_g  = (const float*)d_in[15];
    const float* ln2_b  = (const float*)d_in[16];
    const float* fc1_w  = (const float*)d_in[17];
    const float* fc1_b  = (const float*)d_in[18];
    const float* dw_w   = (const float*)d_in[19];
    const float* dw_b   = (const float*)d_in[20];
    const float* fc2_w  = (const float*)d_in[21];
    const float* fc2_b  = (const float*)d_in[22];
    float* outp = (float*)d_out;

    float *x1, *xn, *q, *k, *v, *lep, *vw, *ao, *x2, *hdn, *hdn2;
    cudaGetSymbolAddress((void**)&x1,   g_x1);
    cudaGetSymbolAddress((void**)&xn,   g_xn);
    cudaGetSymbolAddress((void**)&q,    g_q);
    cudaGetSymbolAddress((void**)&k,    g_k);
    cudaGetSymbolAddress((void**)&v,    g_v);
    cudaGetSymbolAddress((void**)&lep,  g_lep);
    cudaGetSymbolAddress((void**)&vw,   g_vw);
    cudaGetSymbolAddress((void**)&ao,   g_ao);
    cudaGetSymbolAddress((void**)&x2,   g_x2);
    cudaGetSymbolAddress((void**)&hdn,  g_hdn);
    cudaGetSymbolAddress((void**)&hdn2, g_hdn2);

    __nv_bfloat16 *xnh, *xnl, *aoh, *aol, *h2h, *h2l;
    __nv_bfloat16 *wqh, *wql, *wkh, *wkl, *wvh, *wvl, *woh, *wol, *f1h, *f1l, *f2h, *f2l;
    cudaGetSymbolAddress((void**)&xnh, g_xnh); cudaGetSymbolAddress((void**)&xnl, g_xnl);
    cudaGetSymbolAddress((void**)&aoh, g_aoh); cudaGetSymbolAddress((void**)&aol, g_aol);
    cudaGetSymbolAddress((void**)&h2h, g_h2h); cudaGetSymbolAddress((void**)&h2l, g_h2l);
    cudaGetSymbolAddress((void**)&wqh, g_wqh); cudaGetSymbolAddress((void**)&wql, g_wql);
    cudaGetSymbolAddress((void**)&wkh, g_wkh); cudaGetSymbolAddress((void**)&wkl, g_wkl);
    cudaGetSymbolAddress((void**)&wvh, g_wvh); cudaGetSymbolAddress((void**)&wvl, g_wvl);
    cudaGetSymbolAddress((void**)&woh, g_woh); cudaGetSymbolAddress((void**)&wol, g_wol);
    cudaGetSymbolAddress((void**)&f1h, g_f1h); cudaGetSymbolAddress((void**)&f1l, g_f1l);
    cudaGetSymbolAddress((void**)&f2h, g_f2h); cudaGetSymbolAddress((void**)&f2l, g_f2l);

    cudaFuncSetAttribute(hgemm<EPI_QROPE>, cudaFuncAttributeMaxDynamicSharedMemorySize, HG_SMEM);
    cudaFuncSetAttribute(hgemm<EPI_KROPE>, cudaFuncAttributeMaxDynamicSharedMemorySize, HG_SMEM);
    cudaFuncSetAttribute(hgemm<EPI_VSCAT>, cudaFuncAttributeMaxDynamicSharedMemorySize, HG_SMEM);
    cudaFuncSetAttribute(hgemm<EPI_RES>,   cudaFuncAttributeMaxDynamicSharedMemorySize, HG_SMEM);
    cudaFuncSetAttribute(hgemm<EPI_GELU>,  cudaFuncAttributeMaxDynamicSharedMemorySize, HG_SMEM);

    rope_table_kernel<<<(SPAT * 16 + 255) / 256, 256>>>();
    cpe_kernel<<<NPIX * DIM / 256, 256>>>(x, cpe_w, cpe_b, x1);
    ln3_kernel<<<NPIX / 8, 256>>>(x1, ln1_g, ln1_b, xn, xnh, xnl);
    wcvt_kernel<<<DIM * DIM / 256, 256>>>(wq, wqh, wql, DIM * DIM);
    wcvt_kernel<<<DIM * DIM / 256, 256>>>(wk, wkh, wkl, DIM * DIM);
    wcvt_kernel<<<DIM * DIM / 256, 256>>>(wv, wvh, wvl, DIM * DIM);

    dim3 gD(NPIX / 128, DIM / 64);       // 196 x 4
    hgemm<EPI_QROPE><<<gD, 256, HG_SMEM>>>(xn, xnh, xnl, wq, wqh, wql, bq, nullptr, q, DIM, DIM);
    hgemm<EPI_KROPE><<<gD, 256, HG_SMEM>>>(xn, xnh, xnl, wk, wkh, wkl, bk, nullptr, k, DIM, DIM);
    hgemm<EPI_VSCAT><<<gD, 256, HG_SMEM>>>(xn, xnh, xnl, wv, wvh, wvl, bv, nullptr, v, DIM, DIM);

    lepe_kernel<<<NPIX * DIM / 256, 256>>>(v, lepe_w, lepe_b, lep);
    rowattn_kernel<<<BB * NHD * HH, 64>>>(q, k, v, vw);
    colattn_kernel<<<BB * NHD * WW, 64>>>(q, k, vw, lep, ao, aoh, aol);

    wcvt_kernel<<<DIM * DIM / 256, 256>>>(wo, woh, wol, DIM * DIM);
    hgemm<EPI_RES><<<gD, 256, HG_SMEM>>>(ao, aoh, aol, wo, woh, wol, bo, x1, x2, DIM, DIM);

    ln3_kernel<<<NPIX / 8, 256>>>(x2, ln2_g, ln2_b, xn, xnh, xnl);

    dim3 gF(NPIX / 128, FFND / 64);      // 196 x 16
    wcvt_kernel<<<FFND * DIM / 256, 256>>>(fc1_w, f1h, f1l, FFND * DIM);
    hgemm<EPI_GELU><<<gF, 256, HG_SMEM>>>(xn, xnh, xnl, fc1_w, f1h, f1l, fc1_b, nullptr, hdn, DIM, FFND);
    dwffn3_kernel<<<NPIX * FFND / 256, 256>>>(hdn, dw_w, dw_b, hdn2, h2h, h2l);
    wcvt_kernel<<<DIM * FFND / 256, 256>>>(fc2_w, f2h, f2l, DIM * FFND);
    hgemm<EPI_RES><<<gD, 256, HG_SMEM>>>(hdn2, h2h, h2l, fc2_w, f2h, f2l, fc2_b, x2, outp, FFND, DIM);
}

// round 14
// speedup vs baseline: 1.3731x; 1.0938x over previous
#include <cuda_runtime.h>
#include <cuda_bf16.h>
#include <math.h>
#include <stdint.h>

// ---------------- problem constants ----------------
#define BB    8
#define HH    56
#define WW    56
#define DIM   256
#define FFND  1024
#define NHD   8
#define KDIM  32
#define SPAT  (HH*WW)          // 3136
#define NPIX  (BB*SPAT)        // 25088
#define SCALEF 0.17677669529663687f   // 32^-0.5

// ---------------- scratch (device globals; no allocs allowed) ----------------
__device__ float g_x1  [NPIX*DIM];
__device__ float g_xn  [NPIX*DIM];
__device__ float g_q   [NPIX*DIM];
__device__ float g_k   [NPIX*DIM];
__device__ float g_v   [NPIX*DIM];
__device__ float g_lep [NPIX*DIM];
__device__ float g_vw  [NPIX*DIM];
__device__ float g_attn[NPIX*DIM];
__device__ float g_ao  [NPIX*DIM];   // attn + lepe (fp32)
__device__ float g_x2  [NPIX*DIM];
__device__ float g_hdn [NPIX*FFND];
__device__ float g_hdn2[NPIX*FFND];
__device__ float g_sin [SPAT*KDIM];
__device__ float g_cos [SPAT*KDIM];

// bf16 hi/lo split buffers
__device__ __nv_bfloat16 g_xnh[NPIX*DIM],  g_xnl[NPIX*DIM];
__device__ __nv_bfloat16 g_aoh[NPIX*DIM],  g_aol[NPIX*DIM];
__device__ __nv_bfloat16 g_h2h[NPIX*FFND], g_h2l[NPIX*FFND];
__device__ __nv_bfloat16 g_wqh[DIM*DIM],  g_wql[DIM*DIM];
__device__ __nv_bfloat16 g_wkh[DIM*DIM],  g_wkl[DIM*DIM];
__device__ __nv_bfloat16 g_wvh[DIM*DIM],  g_wvl[DIM*DIM];
__device__ __nv_bfloat16 g_woh[DIM*DIM],  g_wol[DIM*DIM];
__device__ __nv_bfloat16 g_f1h[FFND*DIM], g_f1l[FFND*DIM];
__device__ __nv_bfloat16 g_f2h[DIM*FFND], g_f2l[DIM*FFND];

// ---------------- helpers ----------------
__device__ __forceinline__ uint32_t smem_u32(const void* p) {
    uint32_t a;
    asm("{ .reg .u64 t; cvta.to.shared.u64 t, %1; cvt.u32.u64 %0, t; }" : "=r"(a) : "l"(p));
    return a;
}
__device__ __forceinline__ void cpasync16(uint32_t dst, const void* src) {
    asm volatile("cp.async.cg.shared.global [%0], [%1], 16;" :: "r"(dst), "l"(src));
}
#define CP_COMMIT() asm volatile("cp.async.commit_group;" ::: "memory")
#define CP_WAIT(n)  asm volatile("cp.async.wait_group %0;" :: "n"(n) : "memory")
#define BAR(id)     asm volatile("bar.sync %0, 128;" :: "r"(id) : "memory")

__device__ __forceinline__ void ldsm4(uint32_t* r, uint32_t addr) {
    asm volatile("ldmatrix.sync.aligned.m8n8.x4.shared.b16 {%0,%1,%2,%3}, [%4];"
                 : "=r"(r[0]), "=r"(r[1]), "=r"(r[2]), "=r"(r[3]) : "r"(addr));
}
__device__ __forceinline__ void mma16816(float* c, const uint32_t* a, const uint32_t* b) {
    asm volatile("mma.sync.aligned.m16n8k16.row.col.f32.bf16.bf16.f32 "
        "{%0,%1,%2,%3}, {%4,%5,%6,%7}, {%8,%9}, {%0,%1,%2,%3};"
        : "+f"(c[0]), "+f"(c[1]), "+f"(c[2]), "+f"(c[3])
        : "r"(a[0]), "r"(a[1]), "r"(a[2]), "r"(a[3]), "r"(b[0]), "r"(b[1]));
}

// packed fp32 (FFMA2) helpers — validated in R5 (rel_err 7.7e-8)
__device__ __forceinline__ void fma2(unsigned long long& d,
                                     unsigned long long a,
                                     unsigned long long b) {
    asm("fma.rn.f32x2 %0, %1, %2, %0;" : "+l"(d) : "l"(a), "l"(b));
}
__device__ __forceinline__ unsigned long long pack2(float lo, float hi) {
    unsigned long long r;
    asm("mov.b64 %0, {%1, %2};" : "=l"(r) : "f"(lo), "f"(hi));
    return r;
}
__device__ __forceinline__ void unpack2(unsigned long long v, float& lo, float& hi) {
    asm("mov.b64 {%0, %1}, %2;" : "=f"(lo), "=f"(hi) : "l"(v));
}

// ---------------- RoPE table (fp64 for accuracy, tiny) ----------------
__global__ void rope_table_kernel() {
    int i = blockIdx.x * 256 + threadIdx.x;
    if (i >= SPAT * 16) return;
    int pos = i >> 4, t = i & 15;
    double ang = pow(10000.0, -(double)t / 15.0);
    double ph  = (double)pos * ang;
    float s = (float)sin(ph), c = (float)cos(ph);
    int b = pos * KDIM + 2 * t;
    g_sin[b] = s; g_sin[b + 1] = s;
    g_cos[b] = c; g_cos[b + 1] = c;
}

// ---------------- split-convert helpers ----------------
__device__ __forceinline__ void split_bf16(float y, __nv_bfloat16& h, __nv_bfloat16& l) {
    h = __float2bfloat16(y);
    l = __float2bfloat16(y - __bfloat162float(h));
}

__global__ __launch_bounds__(256) void wcvt_kernel(const float* __restrict__ w,
                                                   __nv_bfloat16* __restrict__ h,
                                                   __nv_bfloat16* __restrict__ l, int n) {
    int i = blockIdx.x * 256 + threadIdx.x;
    if (i >= n) return;
    split_bf16(w[i], h[i], l[i]);
}

// y = a + b -> float + hi/lo
__global__ __launch_bounds__(256) void addcvt3_kernel(const float* __restrict__ a,
                                                      const float* __restrict__ b2,
                                                      float* __restrict__ of,
                                                      __nv_bfloat16* __restrict__ h,
                                                      __nv_bfloat16* __restrict__ l) {
    int i = blockIdx.x * 256 + threadIdx.x;
    float y = a[i] + b2[i];
    of[i] = y;
    split_bf16(y, h[i], l[i]);
}

// ---------------- depthwise 3x3 (cpe): out = x + conv(x) + bias ----------------
__global__ __launch_bounds__(256) void cpe_kernel(const float* __restrict__ x,
                                                  const float* __restrict__ kw,
                                                  const float* __restrict__ kb,
                                                  float* __restrict__ out) {
    int idx = blockIdx.x * 256 + threadIdx.x;
    int c = idx & (DIM - 1); int pix = idx >> 8;
    int w = pix % WW; int hb = pix / WW; int h = hb % HH; int b = hb / HH;
    float acc = kb[c];
    #pragma unroll
    for (int kh = 0; kh < 3; kh++) {
        int hh = h + kh - 1; if ((unsigned)hh >= HH) continue;
        #pragma unroll
        for (int kv = 0; kv < 3; kv++) {
            int ww = w + kv - 1; if ((unsigned)ww >= WW) continue;
            acc = fmaf(x[((size_t)b * SPAT + hh * WW + ww) * DIM + c],
                       kw[(kh * 3 + kv) * DIM + c], acc);
        }
    }
    out[idx] = x[idx] + acc;
}

// ---------------- LayerNorm -> float + hi/lo ----------------
__global__ __launch_bounds__(256) void ln3_kernel(const float* __restrict__ x,
                                                  const float* __restrict__ gam,
                                                  const float* __restrict__ bet,
                                                  float* __restrict__ of,
                                                  __nv_bfloat16* __restrict__ oh,
                                                  __nv_bfloat16* __restrict__ ol) {
    int warp = threadIdx.x >> 5, lane = threadIdx.x & 31;
    int pix = blockIdx.x * 8 + warp;
    const float* row = x + (size_t)pix * DIM;
    float v[8], s = 0.f, s2 = 0.f;
    #pragma unroll
    for (int u = 0; u < 8; u++) { v[u] = row[lane + u * 32]; s += v[u]; s2 += v[u] * v[u]; }
    #pragma unroll
    for (int o = 16; o; o >>= 1) {
        s  += __shfl_xor_sync(0xffffffffu, s,  o);
        s2 += __shfl_xor_sync(0xffffffffu, s2, o);
    }
    float mean = s * (1.f / DIM);
    float var  = s2 * (1.f / DIM) - mean * mean;
    float rstd = rsqrtf(var + 1e-6f);
    #pragma unroll
    for (int u = 0; u < 8; u++) {
        int c = lane + u * 32;
        float y = (v[u] - mean) * rstd * gam[c] + bet[c];
        of[(size_t)pix * DIM + c] = y;
        __nv_bfloat16 h, l; split_bf16(y, h, l);
        oh[(size_t)pix * DIM + c] = h;
        ol[(size_t)pix * DIM + c] = l;
    }
}

// ---------------- hybrid GEMM: HMMA warps 0-3 (rows 0-63), FFMA2 warps 4-7 (rows 64-127)
#define EPI_QROPE 0
#define EPI_KROPE 1
#define EPI_VSCAT 2
#define EPI_RES   3
#define EPI_GELU  4

// smem map
#define FF_A      0                       // Asf[16][68] float
#define FF_B      4352                    // Bsf[16][68] float
#define HM_BASE   8704
#define HM_AH     0
#define HM_AL     5120                    // 64*40*2
#define HM_BH     10240
#define HM_BL     15360
#define HM_STAGE  20480
#define HG_SMEM   (8704 + 2*20480)        // 49664

__device__ __forceinline__ float geluf(float x) {
    return 0.5f * x * (1.0f + erff(x * 0.70710678118654752f));
}

template<int EPI>
__global__ __launch_bounds__(256, 2) void hgemm(const float* __restrict__ Af,
                                                const __nv_bfloat16* __restrict__ Ah,
                                                const __nv_bfloat16* __restrict__ Al,
                                                const float* __restrict__ Wf,
                                                const __nv_bfloat16* __restrict__ Wh,
                                                const __nv_bfloat16* __restrict__ Wl,
                                                const float* __restrict__ bias,
                                                const float* __restrict__ res,
                                                float* __restrict__ Cout,
                                                int K, int M) {
    extern __shared__ __align__(16) char smem[];
    const int tid = threadIdx.x, wid = tid >> 5, l = tid & 31;
    const int row0 = blockIdx.x * 128, col0 = blockIdx.y * 64;

    if (wid < 4) {
        // ================= HMMA half: rows row0..row0+63 =================
        const uint32_t sb = smem_u32(smem) + HM_BASE;
        const int wm = wid & 1, wn = wid >> 1;

        float acc[2][4][4];
        #pragma unroll
        for (int mt = 0; mt < 2; mt++)
            #pragma unroll
            for (int nt = 0; nt < 4; nt++)
                #pragma unroll
                for (int e = 0; e < 4; e++) acc[mt][nt][e] = 0.f;

        int a_off[2], b_off[2];
        #pragma unroll
        for (int mt = 0; mt < 2; mt++) {
            int r = wm * 32 + mt * 16 + (l & 7) + ((l >> 3) & 1) * 8;
            a_off[mt] = r * 40 + (l >> 4) * 8;
        }
        #pragma unroll
        for (int nt2 = 0; nt2 < 2; nt2++) {
            int r = wn * 32 + nt2 * 16 + (l & 7) + (l >> 4) * 8;
            b_off[nt2] = r * 40 + ((l >> 3) & 1) * 8;
        }

        const int nstage = K >> 5;
        auto load_stage = [&](int st, int buf) {
            const int k0 = st << 5;
            const uint32_t base = sb + buf * HM_STAGE;
            #pragma unroll
            for (int i = 0; i < 2; i++) {
                int c = tid + i * 128;
                int r = c >> 2, kc = c & 3;
                size_t ga = (size_t)(row0 + r) * K + k0 + kc * 8;
                size_t gb = (size_t)(col0 + r) * K + k0 + kc * 8;
                cpasync16(base + HM_AH + r * 80 + kc * 16, Ah + ga);
                cpasync16(base + HM_AL + r * 80 + kc * 16, Al + ga);
                cpasync16(base + HM_BH + r * 80 + kc * 16, Wh + gb);
                cpasync16(base + HM_BL + r * 80 + kc * 16, Wl + gb);
            }
        };

        load_stage(0, 0);
        CP_COMMIT();
        for (int st = 0; st < nstage; st++) {
            const int buf = st & 1;
            if (st + 1 < nstage) {
                load_stage(st + 1, (st + 1) & 1);
                CP_COMMIT();
                CP_WAIT(1);
            } else {
                CP_WAIT(0);
            }
            BAR(2);
            const uint32_t base = sb + buf * HM_STAGE;
            #pragma unroll
            for (int ks = 0; ks < 2; ks++) {
                uint32_t ah[2][4], al[2][4], bh4[2][4], bl4[2][4];
                #pragma unroll
                for (int mt = 0; mt < 2; mt++) {
                    ldsm4(ah[mt], base + HM_AH + (a_off[mt] + ks * 16) * 2);
                    ldsm4(al[mt], base + HM_AL + (a_off[mt] + ks * 16) * 2);
                }
                #pragma unroll
                for (int nt2 = 0; nt2 < 2; nt2++) {
                    ldsm4(bh4[nt2], base + HM_BH + (b_off[nt2] + ks * 16) * 2);
                    ldsm4(bl4[nt2], base + HM_BL + (b_off[nt2] + ks * 16) * 2);
                }
                #pragma unroll
                for (int mt = 0; mt < 2; mt++)
                    #pragma unroll
                    for (int nt = 0; nt < 4; nt++) {
                        const uint32_t* bh = &bh4[nt >> 1][(nt & 1) * 2];
                        const uint32_t* bl = &bl4[nt >> 1][(nt & 1) * 2];
                        mma16816(acc[mt][nt], ah[mt], bh);
                        mma16816(acc[mt][nt], ah[mt], bl);
                        mma16816(acc[mt][nt], al[mt], bh);
                    }
            }
            BAR(2);
        }

        // ---- HMMA epilogue ----
        #pragma unroll
        for (int mt = 0; mt < 2; mt++) {
            #pragma unroll
            for (int half = 0; half < 2; half++) {
                const int r = row0 + wm * 32 + mt * 16 + (l >> 2) + half * 8;
                if (EPI == EPI_RES) {
                    #pragma unroll
                    for (int nt = 0; nt < 4; nt++) {
                        const int c = col0 + wn * 32 + nt * 8 + (l & 3) * 2;
                        float v0 = acc[mt][nt][half * 2 + 0] + bias[c];
                        float v1 = acc[mt][nt][half * 2 + 1] + bias[c + 1];
                        float2 rv = *(const float2*)(res + (size_t)r * M + c);
                        float2 o; o.x = v0 + rv.x; o.y = v1 + rv.y;
                        *(float2*)(Cout + (size_t)r * M + c) = o;
                    }
                } else if (EPI == EPI_GELU) {
                    #pragma unroll
                    for (int nt = 0; nt < 4; nt++) {
                        const int c = col0 + wn * 32 + nt * 8 + (l & 3) * 2;
                        float2 o;
                        o.x = geluf(acc[mt][nt][half * 2 + 0] + bias[c]);
                        o.y = geluf(acc[mt][nt][half * 2 + 1] + bias[c + 1]);
                        *(float2*)(Cout + (size_t)r * M + c) = o;
                    }
                } else {
                    const int b = r / SPAT, sp = r - b * SPAT;
                    #pragma unroll
                    for (int nt = 0; nt < 4; nt++) {
                        const int c = col0 + wn * 32 + nt * 8 + (l & 3) * 2;
                        float v0 = acc[mt][nt][half * 2 + 0] + bias[c];
                        float v1 = acc[mt][nt][half * 2 + 1] + bias[c + 1];
                        const int n = c >> 5, d = c & 31;
                        float* dst = Cout + (size_t)(b * NHD + n) * (SPAT * KDIM) + sp * KDIM + d;
                        if (EPI == EPI_VSCAT) {
                            dst[0] = v0; dst[1] = v1;
                        } else {
                            if (EPI == EPI_KROPE) { v0 *= SCALEF; v1 *= SCALEF; }
                            float s = g_sin[sp * KDIM + d], co = g_cos[sp * KDIM + d];
                            dst[0] = v0 * co - v1 * s;
                            dst[1] = v1 * co + v0 * s;
                        }
                    }
                }
            }
        }
    } else {
        // ================= FFMA2 half: rows row0+64..row0+127 =================
        float (*Asf)[68] = (float (*)[68])(smem + FF_A);
        float (*Bsf)[68] = (float (*)[68])(smem + FF_B);
        const int t2 = tid - 128;
        const int tx = t2 & 15, ty = t2 >> 4;

        unsigned long long acc2[4][4];   // [m-pair][n]; lo = row 2mp, hi = row 2mp+1
        #pragma unroll
        for (int mp = 0; mp < 4; mp++)
            #pragma unroll
            for (int j = 0; j < 4; j++) acc2[mp][j] = 0ull;

        const int lr = t2 >> 1, lk = (t2 & 1) * 8;
        const size_t aoff = (size_t)(row0 + 64 + lr) * K + lk;
        const size_t boff = (size_t)(col0 + lr) * K + lk;

        float4 a0 = *(const float4*)(Af + aoff);
        float4 a1 = *(const float4*)(Af + aoff + 4);
        float4 b0 = *(const float4*)(Wf + boff);
        float4 b1 = *(const float4*)(Wf + boff + 4);

        for (int k0 = 0; k0 < K; k0 += 16) {
            Asf[lk + 0][lr] = a0.x; Asf[lk + 1][lr] = a0.y;
            Asf[lk + 2][lr] = a0.z; Asf[lk + 3][lr] = a0.w;
            Asf[lk + 4][lr] = a1.x; Asf[lk + 5][lr] = a1.y;
            Asf[lk + 6][lr] = a1.z; Asf[lk + 7][lr] = a1.w;
            Bsf[lk + 0][lr] = b0.x; Bsf[lk + 1][lr] = b0.y;
            Bsf[lk + 2][lr] = b0.z; Bsf[lk + 3][lr] = b0.w;
            Bsf[lk + 4][lr] = b1.x; Bsf[lk + 5][lr] = b1.y;
            Bsf[lk + 6][lr] = b1.z; Bsf[lk + 7][lr] = b1.w;
            BAR(1);

            const int kn = k0 + 16;
            if (kn < K) {
                a0 = *(const float4*)(Af + aoff + kn);
                a1 = *(const float4*)(Af + aoff + kn + 4);
                b0 = *(const float4*)(Wf + boff + kn);
                b1 = *(const float4*)(Wf + boff + kn + 4);
            }

            #pragma unroll
            for (int kk = 0; kk < 16; kk++) {
                const unsigned long long* ap =
                    (const unsigned long long*)&Asf[kk][ty * 8];
                unsigned long long a2r[4];
                a2r[0] = ap[0]; a2r[1] = ap[1]; a2r[2] = ap[2]; a2r[3] = ap[3];
                float4 bv = *(const float4*)&Bsf[kk][tx * 4];
                unsigned long long bd[4];
                bd[0] = pack2(bv.x, bv.x); bd[1] = pack2(bv.y, bv.y);
                bd[2] = pack2(bv.z, bv.z); bd[3] = pack2(bv.w, bv.w);
                #pragma unroll
                for (int mp = 0; mp < 4; mp++)
                    #pragma unroll
                    for (int j = 0; j < 4; j++)
                        fma2(acc2[mp][j], a2r[mp], bd[j]);
            }
            BAR(1);
        }

        // unpack accumulators
        float acc[8][4];
        #pragma unroll
        for (int mp = 0; mp < 4; mp++)
            #pragma unroll
            for (int j = 0; j < 4; j++)
                unpack2(acc2[mp][j], acc[2 * mp][j], acc[2 * mp + 1][j]);

        // ---- FFMA epilogue ----
        #pragma unroll
        for (int i = 0; i < 8; i++) {
            const int r = row0 + 64 + ty * 8 + i;
            if (EPI == EPI_RES) {
                const int c = col0 + tx * 4;
                const float4 rv = *(const float4*)(res + (size_t)r * M + c);
                float4 o;
                o.x = acc[i][0] + bias[c + 0] + rv.x;
                o.y = acc[i][1] + bias[c + 1] + rv.y;
                o.z = acc[i][2] + bias[c + 2] + rv.z;
                o.w = acc[i][3] + bias[c + 3] + rv.w;
                *(float4*)(Cout + (size_t)r * M + c) = o;
            } else if (EPI == EPI_GELU) {
                const int c = col0 + tx * 4;
                float4 o;
                o.x = geluf(acc[i][0] + bias[c + 0]);
                o.y = geluf(acc[i][1] + bias[c + 1]);
                o.z = geluf(acc[i][2] + bias[c + 2]);
                o.w = geluf(acc[i][3] + bias[c + 3]);
                *(float4*)(Cout + (size_t)r * M + c) = o;
            } else {
                const int b = r / SPAT, sp = r - b * SPAT;
                #pragma unroll
                for (int jp = 0; jp < 4; jp += 2) {
                    const int c = col0 + tx * 4 + jp;
                    float v0 = acc[i][jp]     + bias[c];
                    float v1 = acc[i][jp + 1] + bias[c + 1];
                    const int n = c >> 5, d = c & 31;
                    float* dst = Cout + (size_t)(b * NHD + n) * (SPAT * KDIM) + sp * KDIM + d;
                    if (EPI == EPI_VSCAT) {
                        dst[0] = v0; dst[1] = v1;
                    } else {
                        if (EPI == EPI_KROPE) { v0 *= SCALEF; v1 *= SCALEF; }
                        float s = g_sin[sp * KDIM + d], co = g_cos[sp * KDIM + d];
                        dst[0] = v0 * co - v1 * s;
                        dst[1] = v1 * co + v0 * s;
                    }
                }
            }
        }
    }
}

// ---------------- lepe: 5x5 depthwise conv of v ----------------
__global__ __launch_bounds__(256) void lepe_kernel(const float* __restrict__ v,
                                                   const float* __restrict__ kw,
                                                   const float* __restrict__ kb,
                                                   float* __restrict__ out) {
    int idx = blockIdx.x * 256 + threadIdx.x;
    int c = idx & (DIM - 1); int pix = idx >> 8;
    int w = pix % WW; int hb = pix / WW; int h = hb % HH; int b = hb / HH;
    int n = c >> 5, d = c & 31;
    const float* vb = v + (size_t)(b * NHD + n) * (SPAT * KDIM) + d;
    float acc = kb[c];
    #pragma unroll
    for (int kh = 0; kh < 5; kh++) {
        int hh = h + kh - 2; if ((unsigned)hh >= HH) continue;
        #pragma unroll
        for (int kv = 0; kv < 5; kv++) {
            int ww = w + kv - 2; if ((unsigned)ww >= WW) continue;
            acc = fmaf(vb[(hh * WW + ww) * KDIM], kw[(kh * 5 + kv) * DIM + c], acc);
        }
    }
    out[idx] = acc;
}

// ---------------- row attention ----------------
__global__ __launch_bounds__(64) void rowattn_kernel(const float* __restrict__ q,
                                                     const float* __restrict__ k,
                                                     const float* __restrict__ v,
                                                     float* __restrict__ vw) {
    int blk = blockIdx.x;
    int bn = blk / HH, h = blk % HH;
    const size_t base = ((size_t)bn * SPAT + h * WW) * KDIM;
    __shared__ float Ks[WW * KDIM], Vs[WW * KDIM], Ss[WW][57];
    int t = threadIdx.x;
    for (int i = t; i < WW * KDIM; i += 64) { Ks[i] = k[base + i]; Vs[i] = v[base + i]; }
    __syncthreads();
    if (t < WW) {
        float qr[KDIM];
        #pragma unroll
        for (int d = 0; d < KDIM; d++) qr[d] = q[base + t * KDIM + d];
        float mx = -1e30f;
        for (int j = 0; j < WW; j++) {
            float s = 0.f;
            #pragma unroll
            for (int d = 0; d < KDIM; d++) s = fmaf(qr[d], Ks[j * KDIM + d], s);
            Ss[t][j] = s; mx = fmaxf(mx, s);
        }
        float sum = 0.f;
        for (int j = 0; j < WW; j++) { float e = __expf(Ss[t][j] - mx); Ss[t][j] = e; sum += e; }
        float inv = 1.f / sum;
        float acc[KDIM];
        #pragma unroll
        for (int d = 0; d < KDIM; d++) acc[d] = 0.f;
        for (int j = 0; j < WW; j++) {
            float p = Ss[t][j];
            #pragma unroll
            for (int d = 0; d < KDIM; d++) acc[d] = fmaf(p, Vs[j * KDIM + d], acc[d]);
        }
        #pragma unroll
        for (int d = 0; d < KDIM; d++) vw[base + t * KDIM + d] = acc[d] * inv;
    }
}

// ---------------- column attention ----------------
__global__ __launch_bounds__(64) void colattn_kernel(const float* __restrict__ q,
                                                     const float* __restrict__ k,
                                                     const float* __restrict__ vw,
                                                     float* __restrict__ out) {
    int blk = blockIdx.x;
    int bn = blk / WW, w = blk % WW;
    const size_t base = (size_t)bn * (SPAT * KDIM) + w * KDIM;
    __shared__ float Ks[HH * KDIM], Vs[HH * KDIM], Ss[HH][57];
    int t = threadIdx.x;
    for (int i = t; i < HH * KDIM; i += 64) {
        int j = i >> 5, d = i & 31;
        Ks[i] = k[base + (size_t)j * (WW * KDIM) + d];
        Vs[i] = vw[base + (size_t)j * (WW * KDIM) + d];
    }
    __syncthreads();
    if (t < HH) {
        float qr[KDIM];
        #pragma unroll
        for (int d = 0; d < KDIM; d++) qr[d] = q[base + (size_t)t * (WW * KDIM) + d];
        float mx = -1e30f;
        for (int j = 0; j < HH; j++) {
            float s = 0.f;
            #pragma unroll
            for (int d = 0; d < KDIM; d++) s = fmaf(qr[d], Ks[j * KDIM + d], s);
            Ss[t][j] = s; mx = fmaxf(mx, s);
        }
        float sum = 0.f;
        for (int j = 0; j < HH; j++) { float e = __expf(Ss[t][j] - mx); Ss[t][j] = e; sum += e; }
        float inv = 1.f / sum;
        float acc[KDIM];
        #pragma unroll
        for (int d = 0; d < KDIM; d++) acc[d] = 0.f;
        for (int j = 0; j < HH; j++) {
            float p = Ss[t][j];
            #pragma unroll
            for (int d = 0; d < KDIM; d++) acc[d] = fmaf(p, Vs[j * KDIM + d], acc[d]);
        }
        float* dst = out + base + (size_t)t * (WW * KDIM);
        #pragma unroll
        for (int d = 0; d < KDIM; d++) dst[d] = acc[d] * inv;
    }
}

// ---------------- FFN depthwise 3x3 -> float + hi/lo ----------------
__global__ __launch_bounds__(256) void dwffn3_kernel(const float* __restrict__ x,
                                                     const float* __restrict__ kw,
                                                     const float* __restrict__ kb,
                                                     float* __restrict__ of,
                                                     __nv_bfloat16* __restrict__ oh,
                                                     __nv_bfloat16* __restrict__ ol) {
    int idx = blockIdx.x * 256 + threadIdx.x;
    int c = idx & (FFND - 1); int pix = idx >> 10;
    int w = pix % WW; int hb = pix / WW; int h = hb % HH; int b = hb / HH;
    float acc = kb[c];
    #pragma unroll
    for (int kh = 0; kh < 3; kh++) {
        int hh = h + kh - 1; if ((unsigned)hh >= HH) continue;
        #pragma unroll
        for (int kv = 0; kv < 3; kv++) {
            int ww = w + kv - 1; if ((unsigned)ww >= WW) continue;
            acc = fmaf(x[((size_t)b * SPAT + hh * WW + ww) * FFND + c],
                       kw[(kh * 3 + kv) * FFND + c], acc);
        }
    }
    float y = x[idx] + acc;
    of[idx] = y;
    __nv_bfloat16 hi, lo; split_bf16(y, hi, lo);
    oh[idx] = hi; ol[idx] = lo;
}

// ---------------- launch ----------------
extern "C" void kernel_launch(void* const* d_in, const int* in_sizes, int n_in,
                              void* d_out, int out_size) {
    (void)in_sizes; (void)n_in; (void)out_size;
    const float* x      = (const float*)d_in[0];
    const float* cpe_w  = (const float*)d_in[1];
    const float* cpe_b  = (const float*)d_in[2];
    const float* ln1_g  = (const float*)d_in[3];
    const float* ln1_b  = (const float*)d_in[4];
    const float* wq     = (const float*)d_in[5];
    const float* bq     = (const float*)d_in[6];
    const float* wk     = (const float*)d_in[7];
    const float* bk     = (const float*)d_in[8];
    const float* wv     = (const float*)d_in[9];
    const float* bv     = (const float*)d_in[10];
    const float* lepe_w = (const float*)d_in[11];
    const float* lepe_b = (const float*)d_in[12];
    const float* wo     = (const float*)d_in[13];
    const float* bo     = (const float*)d_in[14];
    const float* ln2_g  = (const float*)d_in[15];
    const float* ln2_b  = (const float*)d_in[16];
    const float* fc1_w  = (const float*)d_in[17];
    const float* fc1_b  = (const float*)d_in[18];
    const float* dw_w   = (const float*)d_in[19];
    const float* dw_b   = (const float*)d_in[20];
    const float* fc2_w  = (const float*)d_in[21];
    const float* fc2_b  = (const float*)d_in[22];
    float* outp = (float*)d_out;

    float *x1, *xn, *q, *k, *v, *lep, *vw, *attn, *ao, *x2, *hdn, *hdn2;
    cudaGetSymbolAddress((void**)&x1,   g_x1);
    cudaGetSymbolAddress((void**)&xn,   g_xn);
    cudaGetSymbolAddress((void**)&q,    g_q);
    cudaGetSymbolAddress((void**)&k,    g_k);
    cudaGetSymbolAddress((void**)&v,    g_v);
    cudaGetSymbolAddress((void**)&lep,  g_lep);
    cudaGetSymbolAddress((void**)&vw,   g_vw);
    cudaGetSymbolAddress((void**)&attn, g_attn);
    cudaGetSymbolAddress((void**)&ao,   g_ao);
    cudaGetSymbolAddress((void**)&x2,   g_x2);
    cudaGetSymbolAddress((void**)&hdn,  g_hdn);
    cudaGetSymbolAddress((void**)&hdn2, g_hdn2);

    __nv_bfloat16 *xnh, *xnl, *aoh, *aol, *h2h, *h2l;
    __nv_bfloat16 *wqh, *wql, *wkh, *wkl, *wvh, *wvl, *woh, *wol, *f1h, *f1l, *f2h, *f2l;
    cudaGetSymbolAddress((void**)&xnh, g_xnh); cudaGetSymbolAddress((void**)&xnl, g_xnl);
    cudaGetSymbolAddress((void**)&aoh, g_aoh); cudaGetSymbolAddress((void**)&aol, g_aol);
    cudaGetSymbolAddress((void**)&h2h, g_h2h); cudaGetSymbolAddress((void**)&h2l, g_h2l);
    cudaGetSymbolAddress((void**)&wqh, g_wqh); cudaGetSymbolAddress((void**)&wql, g_wql);
    cudaGetSymbolAddress((void**)&wkh, g_wkh); cudaGetSymbolAddress((void**)&wkl, g_wkl);
    cudaGetSymbolAddress((void**)&wvh, g_wvh); cudaGetSymbolAddress((void**)&wvl, g_wvl);
    cudaGetSymbolAddress((void**)&woh, g_woh); cudaGetSymbolAddress((void**)&wol, g_wol);
    cudaGetSymbolAddress((void**)&f1h, g_f1h); cudaGetSymbolAddress((void**)&f1l, g_f1l);
    cudaGetSymbolAddress((void**)&f2h, g_f2h); cudaGetSymbolAddress((void**)&f2l, g_f2l);

    cudaFuncSetAttribute(hgemm<EPI_QROPE>, cudaFuncAttributeMaxDynamicSharedMemorySize, HG_SMEM);
    cudaFuncSetAttribute(hgemm<EPI_KROPE>, cudaFuncAttributeMaxDynamicSharedMemorySize, HG_SMEM);
    cudaFuncSetAttribute(hgemm<EPI_VSCAT>, cudaFuncAttributeMaxDynamicSharedMemorySize, HG_SMEM);
    cudaFuncSetAttribute(hgemm<EPI_RES>,   cudaFuncAttributeMaxDynamicSharedMemorySize, HG_SMEM);
    cudaFuncSetAttribute(hgemm<EPI_GELU>,  cudaFuncAttributeMaxDynamicSharedMemorySize, HG_SMEM);

    rope_table_kernel<<<(SPAT * 16 + 255) / 256, 256>>>();
    cpe_kernel<<<NPIX * DIM / 256, 256>>>(x, cpe_w, cpe_b, x1);
    ln3_kernel<<<NPIX / 8, 256>>>(x1, ln1_g, ln1_b, xn, xnh, xnl);
    wcvt_kernel<<<DIM * DIM / 256, 256>>>(wq, wqh, wql, DIM * DIM);
    wcvt_kernel<<<DIM * DIM / 256, 256>>>(wk, wkh, wkl, DIM * DIM);
    wcvt_kernel<<<DIM * DIM / 256, 256>>>(wv, wvh, wvl, DIM * DIM);

    dim3 gD(NPIX / 128, DIM / 64);       // 196 x 4
    hgemm<EPI_QROPE><<<gD, 256, HG_SMEM>>>(xn, xnh, xnl, wq, wqh, wql, bq, nullptr, q, DIM, DIM);
    hgemm<EPI_KROPE><<<gD, 256, HG_SMEM>>>(xn, xnh, xnl, wk, wkh, wkl, bk, nullptr, k, DIM, DIM);
    hgemm<EPI_VSCAT><<<gD, 256, HG_SMEM>>>(xn, xnh, xnl, wv, wvh, wvl, bv, nullptr, v, DIM, DIM);

    lepe_kernel<<<NPIX * DIM / 256, 256>>>(v, lepe_w, lepe_b, lep);
    rowattn_kernel<<<BB * NHD * HH, 64>>>(q, k, v, vw);
    colattn_kernel<<<BB * NHD * WW, 64>>>(q, k, vw, attn);

    wcvt_kernel<<<DIM * DIM / 256, 256>>>(wo, woh, wol, DIM * DIM);
    addcvt3_kernel<<<NPIX * DIM / 256, 256>>>(attn, lep, ao, aoh, aol);
    hgemm<EPI_RES><<<gD, 256, HG_SMEM>>>(ao, aoh, aol, wo, woh, wol, bo, x1, x2, DIM, DIM);

    ln3_kernel<<<NPIX / 8, 256>>>(x2, ln2_g, ln2_b, xn, xnh, xnl);

    dim3 gF(NPIX / 128, FFND / 64);      // 196 x 16
    wcvt_kernel<<<FFND * DIM / 256, 256>>>(fc1_w, f1h, f1l, FFND * DIM);
    hgemm<EPI_GELU><<<gF, 256, HG_SMEM>>>(xn, xnh, xnl, fc1_w, f1h, f1l, fc1_b, nullptr, hdn, DIM, FFND);
    dwffn3_kernel<<<NPIX * FFND / 256, 256>>>(hdn, dw_w, dw_b, hdn2, h2h, h2l);
    wcvt_kernel<<<DIM * FFND / 256, 256>>>(fc2_w, f2h, f2l, DIM * FFND);
    hgemm<EPI_RES><<<gD, 256, HG_SMEM>>>(hdn2, h2h, h2l, fc2_w, f2h, f2l, fc2_b, x2, outp, FFND, DIM);
}

// round 15
// speedup vs baseline: 1.3966x; 1.0171x over previous
#include <cuda_runtime.h>
#include <cuda_bf16.h>
#include <math.h>
#include <stdint.h>

// ---------------- problem constants ----------------
#define BB    8
#define HH    56
#define WW    56
#define DIM   256
#define FFND  1024
#define NHD   8
#define KDIM  32
#define SPAT  (HH*WW)          // 3136
#define NPIX  (BB*SPAT)        // 25088
#define SCALEF 0.17677669529663687f   // 32^-0.5

// ---------------- scratch (device globals; no allocs allowed) ----------------
__device__ float g_x1  [NPIX*DIM];
__device__ float g_xn  [NPIX*DIM];
__device__ float g_q   [NPIX*DIM];
__device__ float g_k   [NPIX*DIM];
__device__ float g_v   [NPIX*DIM];
__device__ float g_lep [NPIX*DIM];
__device__ float g_vw  [NPIX*DIM];
__device__ float g_attn[NPIX*DIM];
__device__ float g_ao  [NPIX*DIM];   // attn + lepe (fp32)
__device__ float g_x2  [NPIX*DIM];
__device__ float g_hdn [NPIX*FFND];
__device__ float g_hdn2[NPIX*FFND];
__device__ float g_sin [SPAT*KDIM];
__device__ float g_cos [SPAT*KDIM];

// bf16 hi/lo split buffers
__device__ __nv_bfloat16 g_xnh[NPIX*DIM],  g_xnl[NPIX*DIM];
__device__ __nv_bfloat16 g_aoh[NPIX*DIM],  g_aol[NPIX*DIM];
__device__ __nv_bfloat16 g_h2h[NPIX*FFND], g_h2l[NPIX*FFND];
__device__ __nv_bfloat16 g_wqh[DIM*DIM],  g_wql[DIM*DIM];
__device__ __nv_bfloat16 g_wkh[DIM*DIM],  g_wkl[DIM*DIM];
__device__ __nv_bfloat16 g_wvh[DIM*DIM],  g_wvl[DIM*DIM];
__device__ __nv_bfloat16 g_woh[DIM*DIM],  g_wol[DIM*DIM];
__device__ __nv_bfloat16 g_f1h[FFND*DIM], g_f1l[FFND*DIM];
__device__ __nv_bfloat16 g_f2h[DIM*FFND], g_f2l[DIM*FFND];

// ---------------- helpers ----------------
__device__ __forceinline__ uint32_t smem_u32(const void* p) {
    uint32_t a;
    asm("{ .reg .u64 t; cvta.to.shared.u64 t, %1; cvt.u32.u64 %0, t; }" : "=r"(a) : "l"(p));
    return a;
}
__device__ __forceinline__ void cpasync16(uint32_t dst, const void* src) {
    asm volatile("cp.async.cg.shared.global [%0], [%1], 16;" :: "r"(dst), "l"(src));
}
#define CP_COMMIT() asm volatile("cp.async.commit_group;" ::: "memory")
#define CP_WAIT(n)  asm volatile("cp.async.wait_group %0;" :: "n"(n) : "memory")
#define BAR(id)     asm volatile("bar.sync %0, 128;" :: "r"(id) : "memory")

__device__ __forceinline__ void ldsm4(uint32_t* r, uint32_t addr) {
    asm volatile("ldmatrix.sync.aligned.m8n8.x4.shared.b16 {%0,%1,%2,%3}, [%4];"
                 : "=r"(r[0]), "=r"(r[1]), "=r"(r[2]), "=r"(r[3]) : "r"(addr));
}
__device__ __forceinline__ void mma16816(float* c, const uint32_t* a, const uint32_t* b) {
    asm volatile("mma.sync.aligned.m16n8k16.row.col.f32.bf16.bf16.f32 "
        "{%0,%1,%2,%3}, {%4,%5,%6,%7}, {%8,%9}, {%0,%1,%2,%3};"
        : "+f"(c[0]), "+f"(c[1]), "+f"(c[2]), "+f"(c[3])
        : "r"(a[0]), "r"(a[1]), "r"(a[2]), "r"(a[3]), "r"(b[0]), "r"(b[1]));
}

// packed fp32 (FFMA2) helpers
__device__ __forceinline__ void fma2(unsigned long long& d,
                                     unsigned long long a,
                                     unsigned long long b) {
    asm("fma.rn.f32x2 %0, %1, %2, %0;" : "+l"(d) : "l"(a), "l"(b));
}
__device__ __forceinline__ unsigned long long pack2(float lo, float hi) {
    unsigned long long r;
    asm("mov.b64 %0, {%1, %2};" : "=l"(r) : "f"(lo), "f"(hi));
    return r;
}
__device__ __forceinline__ void unpack2(unsigned long long v, float& lo, float& hi) {
    asm("mov.b64 {%0, %1}, %2;" : "=f"(lo), "=f"(hi) : "l"(v));
}

// ---------------- RoPE table (fp64 for accuracy, tiny) ----------------
__global__ void rope_table_kernel() {
    int i = blockIdx.x * 256 + threadIdx.x;
    if (i >= SPAT * 16) return;
    int pos = i >> 4, t = i & 15;
    double ang = pow(10000.0, -(double)t / 15.0);
    double ph  = (double)pos * ang;
    float s = (float)sin(ph), c = (float)cos(ph);
    int b = pos * KDIM + 2 * t;
    g_sin[b] = s; g_sin[b + 1] = s;
    g_cos[b] = c; g_cos[b + 1] = c;
}

// ---------------- split-convert helpers ----------------
__device__ __forceinline__ void split_bf16(float y, __nv_bfloat16& h, __nv_bfloat16& l) {
    h = __float2bfloat16(y);
    l = __float2bfloat16(y - __bfloat162float(h));
}

__global__ __launch_bounds__(256) void wcvt_kernel(const float* __restrict__ w,
                                                   __nv_bfloat16* __restrict__ h,
                                                   __nv_bfloat16* __restrict__ l, int n) {
    int i = blockIdx.x * 256 + threadIdx.x;
    if (i >= n) return;
    split_bf16(w[i], h[i], l[i]);
}

// y = a + b -> float + hi/lo
__global__ __launch_bounds__(256) void addcvt3_kernel(const float* __restrict__ a,
                                                      const float* __restrict__ b2,
                                                      float* __restrict__ of,
                                                      __nv_bfloat16* __restrict__ h,
                                                      __nv_bfloat16* __restrict__ l) {
    int i = blockIdx.x * 256 + threadIdx.x;
    float y = a[i] + b2[i];
    of[i] = y;
    split_bf16(y, h[i], l[i]);
}

// ---------------- depthwise 3x3 (cpe): out = x + conv(x) + bias ----------------
__global__ __launch_bounds__(256) void cpe_kernel(const float* __restrict__ x,
                                                  const float* __restrict__ kw,
                                                  const float* __restrict__ kb,
                                                  float* __restrict__ out) {
    int idx = blockIdx.x * 256 + threadIdx.x;
    int c = idx & (DIM - 1); int pix = idx >> 8;
    int w = pix % WW; int hb = pix / WW; int h = hb % HH; int b = hb / HH;
    float acc = kb[c];
    #pragma unroll
    for (int kh = 0; kh < 3; kh++) {
        int hh = h + kh - 1; if ((unsigned)hh >= HH) continue;
        #pragma unroll
        for (int kv = 0; kv < 3; kv++) {
            int ww = w + kv - 1; if ((unsigned)ww >= WW) continue;
            acc = fmaf(x[((size_t)b * SPAT + hh * WW + ww) * DIM + c],
                       kw[(kh * 3 + kv) * DIM + c], acc);
        }
    }
    out[idx] = x[idx] + acc;
}

// ---------------- LayerNorm -> float + hi/lo ----------------
__global__ __launch_bounds__(256) void ln3_kernel(const float* __restrict__ x,
                                                  const float* __restrict__ gam,
                                                  const float* __restrict__ bet,
                                                  float* __restrict__ of,
                                                  __nv_bfloat16* __restrict__ oh,
                                                  __nv_bfloat16* __restrict__ ol) {
    int warp = threadIdx.x >> 5, lane = threadIdx.x & 31;
    int pix = blockIdx.x * 8 + warp;
    const float* row = x + (size_t)pix * DIM;
    float v[8], s = 0.f, s2 = 0.f;
    #pragma unroll
    for (int u = 0; u < 8; u++) { v[u] = row[lane + u * 32]; s += v[u]; s2 += v[u] * v[u]; }
    #pragma unroll
    for (int o = 16; o; o >>= 1) {
        s  += __shfl_xor_sync(0xffffffffu, s,  o);
        s2 += __shfl_xor_sync(0xffffffffu, s2, o);
    }
    float mean = s * (1.f / DIM);
    float var  = s2 * (1.f / DIM) - mean * mean;
    float rstd = rsqrtf(var + 1e-6f);
    #pragma unroll
    for (int u = 0; u < 8; u++) {
        int c = lane + u * 32;
        float y = (v[u] - mean) * rstd * gam[c] + bet[c];
        of[(size_t)pix * DIM + c] = y;
        __nv_bfloat16 h, l; split_bf16(y, h, l);
        oh[(size_t)pix * DIM + c] = h;
        ol[(size_t)pix * DIM + c] = l;
    }
}

// ---------------- hybrid GEMM: HMMA warps 0-3 (rows 0-63), FFMA2 warps 4-7 (rows 64-127)
#define EPI_QKV   0
#define EPI_RES   3
#define EPI_GELU  4

// smem map
#define FF_A      0                       // Asf[16][68] float
#define FF_B      4352                    // Bsf[16][68] float
#define HM_BASE   8704
#define HM_AH     0
#define HM_AL     5120                    // 64*40*2
#define HM_BH     10240
#define HM_BL     15360
#define HM_STAGE  20480
#define HG_SMEM   (8704 + 2*20480)        // 49664

__device__ __forceinline__ float geluf(float x) {
    return 0.5f * x * (1.0f + erff(x * 0.70710678118654752f));
}

// EPI_QKV: grid.y = 12; sel = y>>2 picks q/k/v weight set, col0 = (y&3)*64.
//   sel 0 -> rope (scale 1) -> Cout ; sel 1 -> rope*SCALEF -> Cout2 ; sel 2 -> scatter -> Cout3
template<int EPI>
__global__ __launch_bounds__(256, 2) void hgemm(const float* __restrict__ Af,
                                                const __nv_bfloat16* __restrict__ Ah,
                                                const __nv_bfloat16* __restrict__ Al,
                                                const float* __restrict__ Wf,
                                                const __nv_bfloat16* __restrict__ Wh,
                                                const __nv_bfloat16* __restrict__ Wl,
                                                const float* __restrict__ bias,
                                                const float* __restrict__ res,
                                                float* __restrict__ Cout,
                                                const float* Wf2, const __nv_bfloat16* Wh2, const __nv_bfloat16* Wl2,
                                                const float* bias2, float* Cout2,
                                                const float* Wf3, const __nv_bfloat16* Wh3, const __nv_bfloat16* Wl3,
                                                const float* bias3, float* Cout3,
                                                int K, int M) {
    extern __shared__ __align__(16) char smem[];
    const int tid = threadIdx.x, wid = tid >> 5, l = tid & 31;
    const int row0 = blockIdx.x * 128;
    int col0 = blockIdx.y * 64;
    int sel = 0;
    if (EPI == EPI_QKV) {
        sel = blockIdx.y >> 2;
        col0 = (blockIdx.y & 3) * 64;
        if (sel == 1) { Wf = Wf2; Wh = Wh2; Wl = Wl2; bias = bias2; Cout = Cout2; }
        else if (sel == 2) { Wf = Wf3; Wh = Wh3; Wl = Wl3; bias = bias3; Cout = Cout3; }
    }

    if (wid < 4) {
        // ================= HMMA half: rows row0..row0+63 =================
        const uint32_t sb = smem_u32(smem) + HM_BASE;
        const int wm = wid & 1, wn = wid >> 1;

        float acc[2][4][4];
        #pragma unroll
        for (int mt = 0; mt < 2; mt++)
            #pragma unroll
            for (int nt = 0; nt < 4; nt++)
                #pragma unroll
                for (int e = 0; e < 4; e++) acc[mt][nt][e] = 0.f;

        int a_off[2], b_off[2];
        #pragma unroll
        for (int mt = 0; mt < 2; mt++) {
            int r = wm * 32 + mt * 16 + (l & 7) + ((l >> 3) & 1) * 8;
            a_off[mt] = r * 40 + (l >> 4) * 8;
        }
        #pragma unroll
        for (int nt2 = 0; nt2 < 2; nt2++) {
            int r = wn * 32 + nt2 * 16 + (l & 7) + (l >> 4) * 8;
            b_off[nt2] = r * 40 + ((l >> 3) & 1) * 8;
        }

        const int nstage = K >> 5;
        auto load_stage = [&](int st, int buf) {
            const int k0 = st << 5;
            const uint32_t base = sb + buf * HM_STAGE;
            #pragma unroll
            for (int i = 0; i < 2; i++) {
                int c = tid + i * 128;
                int r = c >> 2, kc = c & 3;
                size_t ga = (size_t)(row0 + r) * K + k0 + kc * 8;
                size_t gb = (size_t)(col0 + r) * K + k0 + kc * 8;
                cpasync16(base + HM_AH + r * 80 + kc * 16, Ah + ga);
                cpasync16(base + HM_AL + r * 80 + kc * 16, Al + ga);
                cpasync16(base + HM_BH + r * 80 + kc * 16, Wh + gb);
                cpasync16(base + HM_BL + r * 80 + kc * 16, Wl + gb);
            }
        };

        load_stage(0, 0);
        CP_COMMIT();
        for (int st = 0; st < nstage; st++) {
            const int buf = st & 1;
            if (st + 1 < nstage) {
                load_stage(st + 1, (st + 1) & 1);
                CP_COMMIT();
                CP_WAIT(1);
            } else {
                CP_WAIT(0);
            }
            BAR(2);
            const uint32_t base = sb + buf * HM_STAGE;
            #pragma unroll
            for (int ks = 0; ks < 2; ks++) {
                uint32_t ah[2][4], al[2][4], bh4[2][4], bl4[2][4];
                #pragma unroll
                for (int mt = 0; mt < 2; mt++) {
                    ldsm4(ah[mt], base + HM_AH + (a_off[mt] + ks * 16) * 2);
                    ldsm4(al[mt], base + HM_AL + (a_off[mt] + ks * 16) * 2);
                }
                #pragma unroll
                for (int nt2 = 0; nt2 < 2; nt2++) {
                    ldsm4(bh4[nt2], base + HM_BH + (b_off[nt2] + ks * 16) * 2);
                    ldsm4(bl4[nt2], base + HM_BL + (b_off[nt2] + ks * 16) * 2);
                }
                #pragma unroll
                for (int mt = 0; mt < 2; mt++)
                    #pragma unroll
                    for (int nt = 0; nt < 4; nt++) {
                        const uint32_t* bh = &bh4[nt >> 1][(nt & 1) * 2];
                        const uint32_t* bl = &bl4[nt >> 1][(nt & 1) * 2];
                        mma16816(acc[mt][nt], ah[mt], bh);
                        mma16816(acc[mt][nt], ah[mt], bl);
                        mma16816(acc[mt][nt], al[mt], bh);
                    }
            }
            BAR(2);
        }

        // ---- HMMA epilogue ----
        #pragma unroll
        for (int mt = 0; mt < 2; mt++) {
            #pragma unroll
            for (int half = 0; half < 2; half++) {
                const int r = row0 + wm * 32 + mt * 16 + (l >> 2) + half * 8;
                if (EPI == EPI_RES) {
                    #pragma unroll
                    for (int nt = 0; nt < 4; nt++) {
                        const int c = col0 + wn * 32 + nt * 8 + (l & 3) * 2;
                        float v0 = acc[mt][nt][half * 2 + 0] + bias[c];
                        float v1 = acc[mt][nt][half * 2 + 1] + bias[c + 1];
                        float2 rv = *(const float2*)(res + (size_t)r * M + c);
                        float2 o; o.x = v0 + rv.x; o.y = v1 + rv.y;
                        *(float2*)(Cout + (size_t)r * M + c) = o;
                    }
                } else if (EPI == EPI_GELU) {
                    #pragma unroll
                    for (int nt = 0; nt < 4; nt++) {
                        const int c = col0 + wn * 32 + nt * 8 + (l & 3) * 2;
                        float2 o;
                        o.x = geluf(acc[mt][nt][half * 2 + 0] + bias[c]);
                        o.y = geluf(acc[mt][nt][half * 2 + 1] + bias[c + 1]);
                        *(float2*)(Cout + (size_t)r * M + c) = o;
                    }
                } else {
                    const int b = r / SPAT, sp = r - b * SPAT;
                    #pragma unroll
                    for (int nt = 0; nt < 4; nt++) {
                        const int c = col0 + wn * 32 + nt * 8 + (l & 3) * 2;
                        float v0 = acc[mt][nt][half * 2 + 0] + bias[c];
                        float v1 = acc[mt][nt][half * 2 + 1] + bias[c + 1];
                        const int n = c >> 5, d = c & 31;
                        float* dst = Cout + (size_t)(b * NHD + n) * (SPAT * KDIM) + sp * KDIM + d;
                        if (sel == 2) {
                            dst[0] = v0; dst[1] = v1;
                        } else {
                            if (sel == 1) { v0 *= SCALEF; v1 *= SCALEF; }
                            float s = g_sin[sp * KDIM + d], co = g_cos[sp * KDIM + d];
                            dst[0] = v0 * co - v1 * s;
                            dst[1] = v1 * co + v0 * s;
                        }
                    }
                }
            }
        }
    } else {
        // ================= FFMA2 half: rows row0+64..row0+127 =================
        float (*Asf)[68] = (float (*)[68])(smem + FF_A);
        float (*Bsf)[68] = (float (*)[68])(smem + FF_B);
        const int t2 = tid - 128;
        const int tx = t2 & 15, ty = t2 >> 4;

        unsigned long long acc2[4][4];
        #pragma unroll
        for (int mp = 0; mp < 4; mp++)
            #pragma unroll
            for (int j = 0; j < 4; j++) acc2[mp][j] = 0ull;

        const int lr = t2 >> 1, lk = (t2 & 1) * 8;
        const size_t aoff = (size_t)(row0 + 64 + lr) * K + lk;
        const size_t boff = (size_t)(col0 + lr) * K + lk;

        float4 a0 = *(const float4*)(Af + aoff);
        float4 a1 = *(const float4*)(Af + aoff + 4);
        float4 b0 = *(const float4*)(Wf + boff);
        float4 b1 = *(const float4*)(Wf + boff + 4);

        for (int k0 = 0; k0 < K; k0 += 16) {
            Asf[lk + 0][lr] = a0.x; Asf[lk + 1][lr] = a0.y;
            Asf[lk + 2][lr] = a0.z; Asf[lk + 3][lr] = a0.w;
            Asf[lk + 4][lr] = a1.x; Asf[lk + 5][lr] = a1.y;
            Asf[lk + 6][lr] = a1.z; Asf[lk + 7][lr] = a1.w;
            Bsf[lk + 0][lr] = b0.x; Bsf[lk + 1][lr] = b0.y;
            Bsf[lk + 2][lr] = b0.z; Bsf[lk + 3][lr] = b0.w;
            Bsf[lk + 4][lr] = b1.x; Bsf[lk + 5][lr] = b1.y;
            Bsf[lk + 6][lr] = b1.z; Bsf[lk + 7][lr] = b1.w;
            BAR(1);

            const int kn = k0 + 16;
            if (kn < K) {
                a0 = *(const float4*)(Af + aoff + kn);
                a1 = *(const float4*)(Af + aoff + kn + 4);
                b0 = *(const float4*)(Wf + boff + kn);
                b1 = *(const float4*)(Wf + boff + kn + 4);
            }

            #pragma unroll
            for (int kk = 0; kk < 16; kk++) {
                const unsigned long long* ap =
                    (const unsigned long long*)&Asf[kk][ty * 8];
                unsigned long long a2r[4];
                a2r[0] = ap[0]; a2r[1] = ap[1]; a2r[2] = ap[2]; a2r[3] = ap[3];
                float4 bv = *(const float4*)&Bsf[kk][tx * 4];
                unsigned long long bd[4];
                bd[0] = pack2(bv.x, bv.x); bd[1] = pack2(bv.y, bv.y);
                bd[2] = pack2(bv.z, bv.z); bd[3] = pack2(bv.w, bv.w);
                #pragma unroll
                for (int mp = 0; mp < 4; mp++)
                    #pragma unroll
                    for (int j = 0; j < 4; j++)
                        fma2(acc2[mp][j], a2r[mp], bd[j]);
            }
            BAR(1);
        }

        float acc[8][4];
        #pragma unroll
        for (int mp = 0; mp < 4; mp++)
            #pragma unroll
            for (int j = 0; j < 4; j++)
                unpack2(acc2[mp][j], acc[2 * mp][j], acc[2 * mp + 1][j]);

        // ---- FFMA epilogue ----
        #pragma unroll
        for (int i = 0; i < 8; i++) {
            const int r = row0 + 64 + ty * 8 + i;
            if (EPI == EPI_RES) {
                const int c = col0 + tx * 4;
                const float4 rv = *(const float4*)(res + (size_t)r * M + c);
                float4 o;
                o.x = acc[i][0] + bias[c + 0] + rv.x;
                o.y = acc[i][1] + bias[c + 1] + rv.y;
                o.z = acc[i][2] + bias[c + 2] + rv.z;
                o.w = acc[i][3] + bias[c + 3] + rv.w;
                *(float4*)(Cout + (size_t)r * M + c) = o;
            } else if (EPI == EPI_GELU) {
                const int c = col0 + tx * 4;
                float4 o;
                o.x = geluf(acc[i][0] + bias[c + 0]);
                o.y = geluf(acc[i][1] + bias[c + 1]);
                o.z = geluf(acc[i][2] + bias[c + 2]);
                o.w = geluf(acc[i][3] + bias[c + 3]);
                *(float4*)(Cout + (size_t)r * M + c) = o;
            } else {
                const int b = r / SPAT, sp = r - b * SPAT;
                #pragma unroll
                for (int jp = 0; jp < 4; jp += 2) {
                    const int c = col0 + tx * 4 + jp;
                    float v0 = acc[i][jp]     + bias[c];
                    float v1 = acc[i][jp + 1] + bias[c + 1];
                    const int n = c >> 5, d = c & 31;
                    float* dst = Cout + (size_t)(b * NHD + n) * (SPAT * KDIM) + sp * KDIM + d;
                    if (sel == 2) {
                        dst[0] = v0; dst[1] = v1;
                    } else {
                        if (sel == 1) { v0 *= SCALEF; v1 *= SCALEF; }
                        float s = g_sin[sp * KDIM + d], co = g_cos[sp * KDIM + d];
                        dst[0] = v0 * co - v1 * s;
                        dst[1] = v1 * co + v0 * s;
                    }
                }
            }
        }
    }
}

// ---------------- lepe: 5x5 depthwise conv of v ----------------
__global__ __launch_bounds__(256) void lepe_kernel(const float* __restrict__ v,
                                                   const float* __restrict__ kw,
                                                   const float* __restrict__ kb,
                                                   float* __restrict__ out) {
    int idx = blockIdx.x * 256 + threadIdx.x;
    int c = idx & (DIM - 1); int pix = idx >> 8;
    int w = pix % WW; int hb = pix / WW; int h = hb % HH; int b = hb / HH;
    int n = c >> 5, d = c & 31;
    const float* vb = v + (size_t)(b * NHD + n) * (SPAT * KDIM) + d;
    float acc = kb[c];
    #pragma unroll
    for (int kh = 0; kh < 5; kh++) {
        int hh = h + kh - 2; if ((unsigned)hh >= HH) continue;
        #pragma unroll
        for (int kv = 0; kv < 5; kv++) {
            int ww = w + kv - 2; if ((unsigned)ww >= WW) continue;
            acc = fmaf(vb[(hh * WW + ww) * KDIM], kw[(kh * 5 + kv) * DIM + c], acc);
        }
    }
    out[idx] = acc;
}

// ---------------- row attention ----------------
__global__ __launch_bounds__(64) void rowattn_kernel(const float* __restrict__ q,
                                                     const float* __restrict__ k,
                                                     const float* __restrict__ v,
                                                     float* __restrict__ vw) {
    int blk = blockIdx.x;
    int bn = blk / HH, h = blk % HH;
    const size_t base = ((size_t)bn * SPAT + h * WW) * KDIM;
    __shared__ float Ks[WW * KDIM], Vs[WW * KDIM], Ss[WW][57];
    int t = threadIdx.x;
    for (int i = t; i < WW * KDIM; i += 64) { Ks[i] = k[base + i]; Vs[i] = v[base + i]; }
    __syncthreads();
    if (t < WW) {
        float qr[KDIM];
        #pragma unroll
        for (int d = 0; d < KDIM; d++) qr[d] = q[base + t * KDIM + d];
        float mx = -1e30f;
        for (int j = 0; j < WW; j++) {
            float s = 0.f;
            #pragma unroll
            for (int d = 0; d < KDIM; d++) s = fmaf(qr[d], Ks[j * KDIM + d], s);
            Ss[t][j] = s; mx = fmaxf(mx, s);
        }
        float sum = 0.f;
        for (int j = 0; j < WW; j++) { float e = __expf(Ss[t][j] - mx); Ss[t][j] = e; sum += e; }
        float inv = 1.f / sum;
        float acc[KDIM];
        #pragma unroll
        for (int d = 0; d < KDIM; d++) acc[d] = 0.f;
        for (int j = 0; j < WW; j++) {
            float p = Ss[t][j];
            #pragma unroll
            for (int d = 0; d < KDIM; d++) acc[d] = fmaf(p, Vs[j * KDIM + d], acc[d]);
        }
        #pragma unroll
        for (int d = 0; d < KDIM; d++) vw[base + t * KDIM + d] = acc[d] * inv;
    }
}

// ---------------- column attention ----------------
__global__ __launch_bounds__(64) void colattn_kernel(const float* __restrict__ q,
                                                     const float* __restrict__ k,
                                                     const float* __restrict__ vw,
                                                     float* __restrict__ out) {
    int blk = blockIdx.x;
    int bn = blk / WW, w = blk % WW;
    const size_t base = (size_t)bn * (SPAT * KDIM) + w * KDIM;
    __shared__ float Ks[HH * KDIM], Vs[HH * KDIM], Ss[HH][57];
    int t = threadIdx.x;
    for (int i = t; i < HH * KDIM; i += 64) {
        int j = i >> 5, d = i & 31;
        Ks[i] = k[base + (size_t)j * (WW * KDIM) + d];
        Vs[i] = vw[base + (size_t)j * (WW * KDIM) + d];
    }
    __syncthreads();
    if (t < HH) {
        float qr[KDIM];
        #pragma unroll
        for (int d = 0; d < KDIM; d++) qr[d] = q[base + (size_t)t * (WW * KDIM) + d];
        float mx = -1e30f;
        for (int j = 0; j < HH; j++) {
            float s = 0.f;
            #pragma unroll
            for (int d = 0; d < KDIM; d++) s = fmaf(qr[d], Ks[j * KDIM + d], s);
            Ss[t][j] = s; mx = fmaxf(mx, s);
        }
        float sum = 0.f;
        for (int j = 0; j < HH; j++) { float e = __expf(Ss[t][j] - mx); Ss[t][j] = e; sum += e; }
        float inv = 1.f / sum;
        float acc[KDIM];
        #pragma unroll
        for (int d = 0; d < KDIM; d++) acc[d] = 0.f;
        for (int j = 0; j < HH; j++) {
            float p = Ss[t][j];
            #pragma unroll
            for (int d = 0; d < KDIM; d++) acc[d] = fmaf(p, Vs[j * KDIM + d], acc[d]);
        }
        float* dst = out + base + (size_t)t * (WW * KDIM);
        #pragma unroll
        for (int d = 0; d < KDIM; d++) dst[d] = acc[d] * inv;
    }
}

// ---------------- FFN depthwise 3x3 -> float + hi/lo ----------------
__global__ __launch_bounds__(256) void dwffn3_kernel(const float* __restrict__ x,
                                                     const float* __restrict__ kw,
                                                     const float* __restrict__ kb,
                                                     float* __restrict__ of,
                                                     __nv_bfloat16* __restrict__ oh,
                                                     __nv_bfloat16* __restrict__ ol) {
    int idx = blockIdx.x * 256 + threadIdx.x;
    int c = idx & (FFND - 1); int pix = idx >> 10;
    int w = pix % WW; int hb = pix / WW; int h = hb % HH; int b = hb / HH;
    float acc = kb[c];
    #pragma unroll
    for (int kh = 0; kh < 3; kh++) {
        int hh = h + kh - 1; if ((unsigned)hh >= HH) continue;
        #pragma unroll
        for (int kv = 0; kv < 3; kv++) {
            int ww = w + kv - 1; if ((unsigned)ww >= WW) continue;
            acc = fmaf(x[((size_t)b * SPAT + hh * WW + ww) * FFND + c],
                       kw[(kh * 3 + kv) * FFND + c], acc);
        }
    }
    float y = x[idx] + acc;
    of[idx] = y;
    __nv_bfloat16 hi, lo; split_bf16(y, hi, lo);
    oh[idx] = hi; ol[idx] = lo;
}

// ---------------- launch ----------------
extern "C" void kernel_launch(void* const* d_in, const int* in_sizes, int n_in,
                              void* d_out, int out_size) {
    (void)in_sizes; (void)n_in; (void)out_size;
    const float* x      = (const float*)d_in[0];
    const float* cpe_w  = (const float*)d_in[1];
    const float* cpe_b  = (const float*)d_in[2];
    const float* ln1_g  = (const float*)d_in[3];
    const float* ln1_b  = (const float*)d_in[4];
    const float* wq     = (const float*)d_in[5];
    const float* bq     = (const float*)d_in[6];
    const float* wk     = (const float*)d_in[7];
    const float* bk     = (const float*)d_in[8];
    const float* wv     = (const float*)d_in[9];
    const float* bv     = (const float*)d_in[10];
    const float* lepe_w = (const float*)d_in[11];
    const float* lepe_b = (const float*)d_in[12];
    const float* wo     = (const float*)d_in[13];
    const float* bo     = (const float*)d_in[14];
    const float* ln2_g  = (const float*)d_in[15];
    const float* ln2_b  = (const float*)d_in[16];
    const float* fc1_w  = (const float*)d_in[17];
    const float* fc1_b  = (const float*)d_in[18];
    const float* dw_w   = (const float*)d_in[19];
    const float* dw_b   = (const float*)d_in[20];
    const float* fc2_w  = (const float*)d_in[21];
    const float* fc2_b  = (const float*)d_in[22];
    float* outp = (float*)d_out;

    float *x1, *xn, *q, *k, *v, *lep, *vw, *attn, *ao, *x2, *hdn, *hdn2;
    cudaGetSymbolAddress((void**)&x1,   g_x1);
    cudaGetSymbolAddress((void**)&xn,   g_xn);
    cudaGetSymbolAddress((void**)&q,    g_q);
    cudaGetSymbolAddress((void**)&k,    g_k);
    cudaGetSymbolAddress((void**)&v,    g_v);
    cudaGetSymbolAddress((void**)&lep,  g_lep);
    cudaGetSymbolAddress((void**)&vw,   g_vw);
    cudaGetSymbolAddress((void**)&attn, g_attn);
    cudaGetSymbolAddress((void**)&ao,   g_ao);
    cudaGetSymbolAddress((void**)&x2,   g_x2);
    cudaGetSymbolAddress((void**)&hdn,  g_hdn);
    cudaGetSymbolAddress((void**)&hdn2, g_hdn2);

    __nv_bfloat16 *xnh, *xnl, *aoh, *aol, *h2h, *h2l;
    __nv_bfloat16 *wqh, *wql, *wkh, *wkl, *wvh, *wvl, *woh, *wol, *f1h, *f1l, *f2h, *f2l;
    cudaGetSymbolAddress((void**)&xnh, g_xnh); cudaGetSymbolAddress((void**)&xnl, g_xnl);
    cudaGetSymbolAddress((void**)&aoh, g_aoh); cudaGetSymbolAddress((void**)&aol, g_aol);
    cudaGetSymbolAddress((void**)&h2h, g_h2h); cudaGetSymbolAddress((void**)&h2l, g_h2l);
    cudaGetSymbolAddress((void**)&wqh, g_wqh); cudaGetSymbolAddress((void**)&wql, g_wql);
    cudaGetSymbolAddress((void**)&wkh, g_wkh); cudaGetSymbolAddress((void**)&wkl, g_wkl);
    cudaGetSymbolAddress((void**)&wvh, g_wvh); cudaGetSymbolAddress((void**)&wvl, g_wvl);
    cudaGetSymbolAddress((void**)&woh, g_woh); cudaGetSymbolAddress((void**)&wol, g_wol);
    cudaGetSymbolAddress((void**)&f1h, g_f1h); cudaGetSymbolAddress((void**)&f1l, g_f1l);
    cudaGetSymbolAddress((void**)&f2h, g_f2h); cudaGetSymbolAddress((void**)&f2l, g_f2l);

    cudaFuncSetAttribute(hgemm<EPI_QKV>,  cudaFuncAttributeMaxDynamicSharedMemorySize, HG_SMEM);
    cudaFuncSetAttribute(hgemm<EPI_RES>,  cudaFuncAttributeMaxDynamicSharedMemorySize, HG_SMEM);
    cudaFuncSetAttribute(hgemm<EPI_GELU>, cudaFuncAttributeMaxDynamicSharedMemorySize, HG_SMEM);

    rope_table_kernel<<<(SPAT * 16 + 255) / 256, 256>>>();
    cpe_kernel<<<NPIX * DIM / 256, 256>>>(x, cpe_w, cpe_b, x1);
    ln3_kernel<<<NPIX / 8, 256>>>(x1, ln1_g, ln1_b, xn, xnh, xnl);
    wcvt_kernel<<<DIM * DIM / 256, 256>>>(wq, wqh, wql, DIM * DIM);
    wcvt_kernel<<<DIM * DIM / 256, 256>>>(wk, wkh, wkl, DIM * DIM);
    wcvt_kernel<<<DIM * DIM / 256, 256>>>(wv, wvh, wvl, DIM * DIM);

    dim3 gQKV(NPIX / 128, 12);           // fused q,k,v: 2352 CTAs in one launch
    hgemm<EPI_QKV><<<gQKV, 256, HG_SMEM>>>(xn, xnh, xnl, wq, wqh, wql, bq, nullptr, q,
                                           wk, wkh, wkl, bk, k,
                                           wv, wvh, wvl, bv, v, DIM, DIM);

    lepe_kernel<<<NPIX * DIM / 256, 256>>>(v, lepe_w, lepe_b, lep);
    rowattn_kernel<<<BB * NHD * HH, 64>>>(q, k, v, vw);
    colattn_kernel<<<BB * NHD * WW, 64>>>(q, k, vw, attn);

    dim3 gD(NPIX / 128, DIM / 64);       // 196 x 4
    wcvt_kernel<<<DIM * DIM / 256, 256>>>(wo, woh, wol, DIM * DIM);
    addcvt3_kernel<<<NPIX * DIM / 256, 256>>>(attn, lep, ao, aoh, aol);
    hgemm<EPI_RES><<<gD, 256, HG_SMEM>>>(ao, aoh, aol, wo, woh, wol, bo, x1, x2,
                                         nullptr, nullptr, nullptr, nullptr, nullptr,
                                         nullptr, nullptr, nullptr, nullptr, nullptr, DIM, DIM);

    ln3_kernel<<<NPIX / 8, 256>>>(x2, ln2_g, ln2_b, xn, xnh, xnl);

    dim3 gF(NPIX / 128, FFND / 64);      // 196 x 16
    wcvt_kernel<<<FFND * DIM / 256, 256>>>(fc1_w, f1h, f1l, FFND * DIM);
    hgemm<EPI_GELU><<<gF, 256, HG_SMEM>>>(xn, xnh, xnl, fc1_w, f1h, f1l, fc1_b, nullptr, hdn,
                                          nullptr, nullptr, nullptr, nullptr, nullptr,
                                          nullptr, nullptr, nullptr, nullptr, nullptr, DIM, FFND);
    dwffn3_kernel<<<NPIX * FFND / 256, 256>>>(hdn, dw_w, dw_b, hdn2, h2h, h2l);
    wcvt_kernel<<<DIM * FFND / 256, 256>>>(fc2_w, f2h, f2l, DIM * FFND);
    hgemm<EPI_RES><<<gD, 256, HG_SMEM>>>(hdn2, h2h, h2l, fc2_w, f2h, f2l, fc2_b, x2, outp,
                                         nullptr, nullptr, nullptr, nullptr, nullptr,
                                         nullptr, nullptr, nullptr, nullptr, nullptr, FFND, DIM);
}